// round 8
// baseline (speedup 1.0000x reference)
#include <cuda_runtime.h>
#include <cuda_fp16.h>
#include <cuda_bf16.h>

// Problem constants
#define BB 64
#define TT 512
#define EE 768
#define HH 128      // hidden per direction
#define KK 11

// ---------------------------------------------------------------------------
// Scratch (device globals; no dynamic allocation allowed)
// ---------------------------------------------------------------------------
__device__ __half g_XPh[(size_t)TT * BB * 1024];  // gate x-contributions (fp16)
__device__ __half g_H0h[(size_t)TT * BB * 256];   // layer0 h (fp16, gemm1 A)
__device__ __half g_H1h[(size_t)TT * BB * 256];   // layer1 h (fp16, crf input)
__device__ float  g_ND[BB];                       // num - den per batch

__device__ __forceinline__ float tanha(float x) {
    float r; asm("tanh.approx.f32 %0, %1;" : "=f"(r) : "f"(x)); return r;
}
__device__ __forceinline__ float sigt(float x) {   // sigmoid via tanh
    return fmaf(0.5f, tanha(0.5f * x), 0.5f);
}
__device__ __forceinline__ __half2 u2h2(unsigned int u) {
    __half2 r; *reinterpret_cast<unsigned int*>(&r) = u; return r;
}
__device__ __forceinline__ unsigned h2u(__half2 h) {
    return *reinterpret_cast<unsigned*>(&h);
}
__device__ __forceinline__ void mma_f16(float* d, const unsigned* a, const unsigned* b) {
    asm volatile(
        "mma.sync.aligned.m16n8k16.row.col.f32.f16.f16.f32 "
        "{%0,%1,%2,%3},{%4,%5,%6,%7},{%8,%9},{%0,%1,%2,%3};"
        : "+f"(d[0]), "+f"(d[1]), "+f"(d[2]), "+f"(d[3])
        : "r"(a[0]), "r"(a[1]), "r"(a[2]), "r"(a[3]), "r"(b[0]), "r"(b[1]));
}

// ---------------------------------------------------------------------------
// fp16 tensor-core GEMM (fp32 accum): XPh[r][n] = A[r][:].W[n][:] + bias[n]
//   r = t*64+b;  AMODE 0: A=embeds (B,T,E) fp32, row r -> ((r&63)*512+(r>>6))*768
//                AMODE 1: A=g_H0h (row-major 256, fp16)
//   n<512 -> W0/bias0 (fwd), else W1/bias1 (rev)
// Tile BM=128, BN=128, BK=16; 8 warps (2m x 4n), warp tile 64x32.
// SMEM: half2 k2-major [k2][m], stride 136 (conflict-free frags), double buffer.
// ---------------------------------------------------------------------------
#define GBK 16
#define HSTR 136

template<int AMODE>
__global__ __launch_bounds__(256) void gemm_tc(
    const float* __restrict__ Aext, int Kdim,
    const float* __restrict__ W0, const float* __restrict__ W1,
    const float* __restrict__ bi0, const float* __restrict__ bh0,
    const float* __restrict__ bi1, const float* __restrict__ bh1)
{
    __shared__ unsigned As2[2][8 * HSTR];
    __shared__ unsigned Bs2[2][8 * HSTR];
    __shared__ float bias[128];

    const int tid  = threadIdx.x;
    const int lane = tid & 31, wid = tid >> 5;
    const int wm = wid >> 2, wn = wid & 3;        // 2 x 4 warp grid
    const int g = lane >> 2, tig = lane & 3;
    const int row0 = blockIdx.y * 128;
    const int col0 = blockIdx.x * 128;

    if (tid < 128) {
        int n = col0 + tid;
        bias[tid] = (n < 512) ? (bi0[n] + bh0[n]) : (bi1[n - 512] + bh1[n - 512]);
    }

    // global load mapping: per thread 8 values of A, 8 of B per 16-k tile
    const int arow = tid >> 1;             // 0..127
    const int ak   = (tid & 1) * 8;        // 0 or 8
    const int ak2  = ak >> 1;              // 0 or 4
    size_t aoff;
    {
        int r = row0 + arow;
        aoff = (AMODE == 0) ? ((size_t)(r & 63) * 512 + (size_t)(r >> 6)) * 768
                            : (size_t)r * 256;
    }
    const float* Af = Aext;
    const __half* Ah = g_H0h;
    const int nG = col0 + arow;
    const float* wrow = (nG < 512) ? (W0 + (size_t)nG * Kdim)
                                   : (W1 + (size_t)(nG - 512) * Kdim);

    float c[4][4][4];
#pragma unroll
    for (int i = 0; i < 4; i++)
#pragma unroll
        for (int j = 0; j < 4; j++)
#pragma unroll
            for (int q = 0; q < 4; q++) c[i][j][q] = 0.f;

    const int niter = Kdim / GBK;

    float4 av0, av1;     // AMODE 0
    uint4  au0;          // AMODE 1
    float4 bv0, bv1;

    // ---- prologue: tile 0 -> buf 0
    if (AMODE == 0) {
        av0 = *reinterpret_cast<const float4*>(Af + aoff + ak);
        av1 = *reinterpret_cast<const float4*>(Af + aoff + ak + 4);
    } else {
        au0 = *reinterpret_cast<const uint4*>(Ah + aoff + ak);
    }
    bv0 = *reinterpret_cast<const float4*>(wrow + ak);
    bv1 = *reinterpret_cast<const float4*>(wrow + ak + 4);

    if (AMODE == 0) {
        As2[0][(ak2 + 0) * HSTR + arow] = h2u(__floats2half2_rn(av0.x, av0.y));
        As2[0][(ak2 + 1) * HSTR + arow] = h2u(__floats2half2_rn(av0.z, av0.w));
        As2[0][(ak2 + 2) * HSTR + arow] = h2u(__floats2half2_rn(av1.x, av1.y));
        As2[0][(ak2 + 3) * HSTR + arow] = h2u(__floats2half2_rn(av1.z, av1.w));
    } else {
        As2[0][(ak2 + 0) * HSTR + arow] = au0.x;
        As2[0][(ak2 + 1) * HSTR + arow] = au0.y;
        As2[0][(ak2 + 2) * HSTR + arow] = au0.z;
        As2[0][(ak2 + 3) * HSTR + arow] = au0.w;
    }
    Bs2[0][(ak2 + 0) * HSTR + arow] = h2u(__floats2half2_rn(bv0.x, bv0.y));
    Bs2[0][(ak2 + 1) * HSTR + arow] = h2u(__floats2half2_rn(bv0.z, bv0.w));
    Bs2[0][(ak2 + 2) * HSTR + arow] = h2u(__floats2half2_rn(bv1.x, bv1.y));
    Bs2[0][(ak2 + 3) * HSTR + arow] = h2u(__floats2half2_rn(bv1.z, bv1.w));
    __syncthreads();

#pragma unroll 1
    for (int i = 0; i < niter; ++i) {
        const int pb = i & 1;
        if (i + 1 < niter) {
            const int k0 = (i + 1) * GBK;
            if (AMODE == 0) {
                av0 = *reinterpret_cast<const float4*>(Af + aoff + k0 + ak);
                av1 = *reinterpret_cast<const float4*>(Af + aoff + k0 + ak + 4);
            } else {
                au0 = *reinterpret_cast<const uint4*>(Ah + aoff + k0 + ak);
            }
            bv0 = *reinterpret_cast<const float4*>(wrow + k0 + ak);
            bv1 = *reinterpret_cast<const float4*>(wrow + k0 + ak + 4);
        }

        // compute tile i from buf pb
        {
            unsigned af[4][4], bf[4][2];
#pragma unroll
            for (int mt = 0; mt < 4; ++mt) {
                int m0 = wm * 64 + mt * 16;
                af[mt][0] = As2[pb][tig * HSTR + m0 + g];
                af[mt][1] = As2[pb][tig * HSTR + m0 + g + 8];
                af[mt][2] = As2[pb][(tig + 4) * HSTR + m0 + g];
                af[mt][3] = As2[pb][(tig + 4) * HSTR + m0 + g + 8];
            }
#pragma unroll
            for (int nt = 0; nt < 4; ++nt) {
                int n0 = wn * 32 + nt * 8;
                bf[nt][0] = Bs2[pb][tig * HSTR + n0 + g];
                bf[nt][1] = Bs2[pb][(tig + 4) * HSTR + n0 + g];
            }
#pragma unroll
            for (int mt = 0; mt < 4; ++mt)
#pragma unroll
                for (int nt = 0; nt < 4; ++nt)
                    mma_f16(c[mt][nt], af[mt], bf[nt]);
        }

        if (i + 1 < niter) {
            const int nb = pb ^ 1;
            if (AMODE == 0) {
                As2[nb][(ak2 + 0) * HSTR + arow] = h2u(__floats2half2_rn(av0.x, av0.y));
                As2[nb][(ak2 + 1) * HSTR + arow] = h2u(__floats2half2_rn(av0.z, av0.w));
                As2[nb][(ak2 + 2) * HSTR + arow] = h2u(__floats2half2_rn(av1.x, av1.y));
                As2[nb][(ak2 + 3) * HSTR + arow] = h2u(__floats2half2_rn(av1.z, av1.w));
            } else {
                As2[nb][(ak2 + 0) * HSTR + arow] = au0.x;
                As2[nb][(ak2 + 1) * HSTR + arow] = au0.y;
                As2[nb][(ak2 + 2) * HSTR + arow] = au0.z;
                As2[nb][(ak2 + 3) * HSTR + arow] = au0.w;
            }
            Bs2[nb][(ak2 + 0) * HSTR + arow] = h2u(__floats2half2_rn(bv0.x, bv0.y));
            Bs2[nb][(ak2 + 1) * HSTR + arow] = h2u(__floats2half2_rn(bv0.z, bv0.w));
            Bs2[nb][(ak2 + 2) * HSTR + arow] = h2u(__floats2half2_rn(bv1.x, bv1.y));
            Bs2[nb][(ak2 + 3) * HSTR + arow] = h2u(__floats2half2_rn(bv1.z, bv1.w));
        }
        __syncthreads();
    }

    // epilogue: XPh(row,col) = c + bias, packed half2 (fp16 XP saves gemm traffic)
#pragma unroll
    for (int mt = 0; mt < 4; ++mt) {
#pragma unroll
        for (int nt = 0; nt < 4; ++nt) {
            int r  = row0 + wm * 64 + mt * 16 + g;
            int cb = wn * 32 + nt * 8 + 2 * tig;
            int col = col0 + cb;
            unsigned p0 = h2u(__floats2half2_rn(c[mt][nt][0] + bias[cb],
                                                c[mt][nt][1] + bias[cb + 1]));
            unsigned p1 = h2u(__floats2half2_rn(c[mt][nt][2] + bias[cb],
                                                c[mt][nt][3] + bias[cb + 1]));
            *reinterpret_cast<unsigned*>(&g_XPh[(size_t)r * 1024 + col]) = p0;
            *reinterpret_cast<unsigned*>(&g_XPh[(size_t)(r + 8) * 1024 + col]) = p1;
        }
    }
}

// ---------------------------------------------------------------------------
// LSTM recurrence: one block per (batch, dir). 512 threads = 16 warps.
// Warp w, lane l: hidden unit u = w*8 + (l&7), gate = l>>3.
// Weights in registers (fp16); h double-buffered in SMEM; tanh.approx
// activations applied pre-shfl; 4 independent half2 chains; pointer marching.
// xp kept as __half through the combine (2 HADD + 1 F2F — no float widening).
// ---------------------------------------------------------------------------
__global__ __launch_bounds__(512) void lstm_kernel(
    const float* __restrict__ whh_fwd, const float* __restrict__ whh_rev, int layer)
{
    __shared__ uint4 hbuf4[2][16];   // 2 x 128 halves

    const int b   = blockIdx.x >> 1;
    const int dir = blockIdx.x & 1;
    const float* whh = dir ? whh_rev : whh_fwd;

    const int lane = threadIdx.x & 31;
    const int wid  = threadIdx.x >> 5;
    const int u    = wid * 8 + (lane & 7);
    const int gate = lane >> 3;
    const int wrow_idx = gate * 128 + u;

    // weights -> registers (fp16)
    __half2 W[64];
    {
        const float4* wr4 = reinterpret_cast<const float4*>(whh + (size_t)wrow_idx * 128);
#pragma unroll
        for (int i = 0; i < 32; ++i) {
            float4 f = wr4[i];
            W[2 * i]     = __floats2half2_rn(f.x, f.y);
            W[2 * i + 1] = __floats2half2_rn(f.z, f.w);
        }
    }
    if (threadIdx.x < 16) hbuf4[0][threadIdx.x] = make_uint4(0u, 0u, 0u, 0u);
    float cst = 0.f;
    __syncthreads();

    const long xstride = dir ? -(long)(BB * 1024) : (long)(BB * 1024);
    const long hstride = dir ? -(long)(BB * 256)  : (long)(BB * 256);
    const size_t hbase = (size_t)(dir ? (TT - 1) : 0) * (BB * 256)
                       + (size_t)b * 256 + dir * 128 + u;
    const __half* xp_p = g_XPh + (size_t)(dir ? (TT - 1) : 0) * (BB * 1024)
                               + (size_t)b * 1024 + dir * 512 + wrow_idx;
    __half* hout_p = (layer ? g_H1h : g_H0h) + hbase;

    __half xp = *xp_p;

    for (int t = 0; t < TT; ++t) {
        // prefetch next step's xp (clamped pointer on last step)
        const __half* pf = xp_p + ((t < TT - 1) ? xstride : 0);
        __half xpn = *pf;

        const uint4* hb = hbuf4[t & 1];
        __half2 s0 = __floats2half2_rn(0.f, 0.f);
        __half2 s1 = s0, s2 = s0, s3 = s0;
#pragma unroll
        for (int k = 0; k < 4; ++k) {
            uint4 ha = hb[4 * k];
            uint4 hc = hb[4 * k + 1];
            uint4 hd = hb[4 * k + 2];
            uint4 he = hb[4 * k + 3];
            s0 = __hfma2(W[16 * k + 0],  u2h2(ha.x), s0);
            s1 = __hfma2(W[16 * k + 1],  u2h2(ha.y), s1);
            s2 = __hfma2(W[16 * k + 2],  u2h2(ha.z), s2);
            s3 = __hfma2(W[16 * k + 3],  u2h2(ha.w), s3);
            s0 = __hfma2(W[16 * k + 4],  u2h2(hc.x), s0);
            s1 = __hfma2(W[16 * k + 5],  u2h2(hc.y), s1);
            s2 = __hfma2(W[16 * k + 6],  u2h2(hc.z), s2);
            s3 = __hfma2(W[16 * k + 7],  u2h2(hc.w), s3);
            s0 = __hfma2(W[16 * k + 8],  u2h2(hd.x), s0);
            s1 = __hfma2(W[16 * k + 9],  u2h2(hd.y), s1);
            s2 = __hfma2(W[16 * k + 10], u2h2(hd.z), s2);
            s3 = __hfma2(W[16 * k + 11], u2h2(hd.w), s3);
            s0 = __hfma2(W[16 * k + 12], u2h2(he.x), s0);
            s1 = __hfma2(W[16 * k + 13], u2h2(he.y), s1);
            s2 = __hfma2(W[16 * k + 14], u2h2(he.z), s2);
            s3 = __hfma2(W[16 * k + 15], u2h2(he.w), s3);
        }
        // half-only combine: hadd2 tree -> lane sum -> + xp -> single F2F
        __half2 sh = __hadd2(__hadd2(s0, s1), __hadd2(s2, s3));
        __half  gh = __hadd(__hadd(__low2half(sh), __high2half(sh)), xp);
        const float gval = __half2float(gh);

        // activation by owning lane: tanh for gate 2, sigmoid (via tanh) else
        const float act = (gate == 2) ? tanha(gval) : sigt(gval);

        const int src = lane & 7;
        float iv = __shfl_sync(0xffffffffu, act, src);
        float fv = __shfl_sync(0xffffffffu, act, src + 8);
        float gv = __shfl_sync(0xffffffffu, act, src + 16);
        float ov = __shfl_sync(0xffffffffu, act, src + 24);

        if (lane < 8) {
            float cn = fv * cst + iv * gv;
            cst = cn;
            float hn = ov * tanha(cn);
            __half hcvt = __float2half_rn(hn);
            reinterpret_cast<__half*>(&hbuf4[(t & 1) ^ 1][0])[u] = hcvt;
            *hout_p = hcvt;
        }
        xp = xpn;
        xp_p += xstride;
        hout_p += hstride;
        __syncthreads();
    }
}

// ---------------------------------------------------------------------------
// CRF (fused emissions): one block per batch.
//  Phase 1: ems[t][n] = H1h[t*64+b][:] . lw[n][:] + lb[n]  (n<11, padded 12)
//  Phase 2: numerator (parallel over t), denominator (warp 0 forward algo)
// ---------------------------------------------------------------------------
__global__ __launch_bounds__(256) void crf_kernel(
    const int* __restrict__ tags, const void* __restrict__ maskraw,
    const float* __restrict__ start_t, const float* __restrict__ end_t,
    const float* __restrict__ trans,
    const float* __restrict__ lw, const float* __restrict__ lb)
{
    __shared__ float ems[TT * 12];
    __shared__ float redf[256];
    __shared__ int   redi[256];
    __shared__ unsigned char maskb[TT];
    __shared__ float s_num;

    const int b = blockIdx.x;
    const int tid = threadIdx.x;

    {
        const unsigned char* mc = reinterpret_cast<const unsigned char*>(maskraw);
        const bool bytewise = (mc[1] != 0);
        const int* mi = reinterpret_cast<const int*>(maskraw);
        for (int t = tid; t < TT; t += 256) {
            maskb[t] = bytewise ? (mc[(size_t)b * TT + t] != 0)
                                : (mi[(size_t)b * TT + t] != 0);
        }
    }

    // ---- fused emissions: 512 x 16 work items (n = item & 15, t = item >> 4)
    for (int base = tid; base < TT * 16; base += 256) {
        int t = base >> 4, n = base & 15;
        if (n < KK) {
            const uint4*  h4 = reinterpret_cast<const uint4*>(
                &g_H1h[((size_t)t * BB + b) * 256]);
            const float4* w4 = reinterpret_cast<const float4*>(lw + (size_t)n * 256);
            float acc = 0.f;
#pragma unroll 8
            for (int k = 0; k < 32; ++k) {
                uint4 hv = h4[k];
                float4 w0 = w4[2 * k], w1 = w4[2 * k + 1];
                float2 a0 = __half22float2(u2h2(hv.x));
                float2 a1 = __half22float2(u2h2(hv.y));
                float2 a2 = __half22float2(u2h2(hv.z));
                float2 a3 = __half22float2(u2h2(hv.w));
                acc += a0.x * w0.x + a0.y * w0.y + a1.x * w0.z + a1.y * w0.w;
                acc += a2.x * w1.x + a2.y * w1.y + a3.x * w1.z + a3.y * w1.w;
            }
            ems[t * 12 + n] = acc + lb[n];
        }
    }
    __syncthreads();

    // ---- numerator (parallel over t)
    float part = 0.f;
    int   cnt  = 0;
    for (int t = tid; t < TT; t += 256) cnt += maskb[t] ? 1 : 0;
    for (int t = 1 + tid; t < TT; t += 256) {
        if (maskb[t]) {
            int tp = tags[(size_t)b * TT + t - 1];
            int tc = tags[(size_t)b * TT + t];
            part += trans[tp * KK + tc] + ems[t * 12 + tc];
        }
    }
    redf[tid] = part; redi[tid] = cnt;
    __syncthreads();
    for (int s = 128; s > 0; s >>= 1) {
        if (tid < s) { redf[tid] += redf[tid + s]; redi[tid] += redi[tid + s]; }
        __syncthreads();
    }
    if (tid == 0) {
        int t0 = tags[(size_t)b * TT];
        int seqEnd = redi[0] - 1;
        s_num = start_t[t0] + ems[t0] + redf[0]
              + end_t[tags[(size_t)b * TT + seqEnd]];
    }
    __syncthreads();

    // ---- denominator (warp 0 forward algorithm)
    if (tid < 32) {
        const int lane = tid;
        float tcol[KK];
        if (lane < KK) {
#pragma unroll
            for (int i = 0; i < KK; i++) tcol[i] = trans[i * KK + lane];
        } else {
#pragma unroll
            for (int i = 0; i < KK; i++) tcol[i] = 0.f;
        }
        float score = (lane < KK) ? (start_t[lane] + ems[lane]) : -1e30f;

        for (int t = 1; t < TT; ++t) {
            if (maskb[t]) {
                float vi[KK];
                float m = -1e30f;
#pragma unroll
                for (int i = 0; i < KK; i++) {
                    float si = __shfl_sync(0xffffffffu, score, i);
                    vi[i] = si + tcol[i];
                    m = fmaxf(m, vi[i]);
                }
                float ssum = 0.f;
#pragma unroll
                for (int i = 0; i < KK; i++) ssum += __expf(vi[i] - m);
                float nxt = m + __logf(ssum) + ems[t * 12 + lane];
                if (lane < KK) score = nxt;
            }
        }
        float v = (lane < KK) ? (score + end_t[lane]) : -1e30f;
        float m = v;
#pragma unroll
        for (int off = 16; off > 0; off >>= 1)
            m = fmaxf(m, __shfl_xor_sync(0xffffffffu, m, off));
        float e = __expf(v - m);
#pragma unroll
        for (int off = 16; off > 0; off >>= 1)
            e += __shfl_xor_sync(0xffffffffu, e, off);
        float den = m + __logf(e);
        if (lane == 0) g_ND[b] = s_num - den;
    }
}

__global__ void finish_kernel(float* __restrict__ out, int out_n)
{
    __shared__ float s[64];
    int tid = threadIdx.x;
    s[tid] = g_ND[tid];
    __syncthreads();
    for (int st = 32; st > 0; st >>= 1) {
        if (tid < st) s[tid] += s[tid + st];
        __syncthreads();
    }
    if (tid == 0) out[0] = -s[0] / 64.f;
    if (tid > 0 && tid < out_n) out[tid] = 0.f;
}

// ---------------------------------------------------------------------------
extern "C" void kernel_launch(void* const* d_in, const int* in_sizes, int n_in,
                              void* d_out, int out_size)
{
    const float* embeds    = (const float*)d_in[0];
    const int*   tags      = (const int*)d_in[1];
    const void*  mask      = d_in[2];
    const float* w_ih_l0   = (const float*)d_in[3];
    const float* w_hh_l0   = (const float*)d_in[4];
    const float* b_ih_l0   = (const float*)d_in[5];
    const float* b_hh_l0   = (const float*)d_in[6];
    const float* w_ih_l0r  = (const float*)d_in[7];
    const float* w_hh_l0r  = (const float*)d_in[8];
    const float* b_ih_l0r  = (const float*)d_in[9];
    const float* b_hh_l0r  = (const float*)d_in[10];
    const float* w_ih_l1   = (const float*)d_in[11];
    const float* w_hh_l1   = (const float*)d_in[12];
    const float* b_ih_l1   = (const float*)d_in[13];
    const float* b_hh_l1   = (const float*)d_in[14];
    const float* w_ih_l1r  = (const float*)d_in[15];
    const float* w_hh_l1r  = (const float*)d_in[16];
    const float* b_ih_l1r  = (const float*)d_in[17];
    const float* b_hh_l1r  = (const float*)d_in[18];
    const float* linear_w  = (const float*)d_in[19];
    const float* linear_b  = (const float*)d_in[20];
    const float* start_tr  = (const float*)d_in[21];
    const float* end_tr    = (const float*)d_in[22];
    const float* trans     = (const float*)d_in[23];
    (void)in_sizes; (void)n_in;

    dim3 ggrid(8, 256);   // N/128 x M/128

    // layer 0
    gemm_tc<0><<<ggrid, 256>>>(embeds, 768,
                               w_ih_l0, w_ih_l0r, b_ih_l0, b_hh_l0, b_ih_l0r, b_hh_l0r);
    lstm_kernel<<<128, 512>>>(w_hh_l0, w_hh_l0r, 0);

    // layer 1 (A = g_H0h, fp16)
    gemm_tc<1><<<ggrid, 256>>>(nullptr, 256,
                               w_ih_l1, w_ih_l1r, b_ih_l1, b_hh_l1, b_ih_l1r, b_hh_l1r);
    lstm_kernel<<<128, 512>>>(w_hh_l1, w_hh_l1r, 1);

    // fused emissions + CRF
    crf_kernel<<<64, 256>>>(tags, mask, start_tr, end_tr, trans, linear_w, linear_b);
    finish_kernel<<<1, 64>>>((float*)d_out, out_size);
}

// round 9
// speedup vs baseline: 1.0412x; 1.0412x over previous
#include <cuda_runtime.h>
#include <cuda_fp16.h>
#include <cuda_bf16.h>

// Problem constants
#define BB 64
#define TT 512
#define EE 768
#define HH 128      // hidden per direction
#define KK 11

// ---------------------------------------------------------------------------
// Scratch (device globals; no dynamic allocation allowed)
// ---------------------------------------------------------------------------
__device__ __half g_XPh[(size_t)TT * BB * 1024];  // gate x-contributions (fp16)
__device__ __half g_H0h[(size_t)TT * BB * 256];   // layer0 h (fp16, gemm1 A)
__device__ __half g_H1h[(size_t)TT * BB * 256];   // layer1 h (fp16, crf input)
__device__ float  g_ND[BB];                       // num - den per batch

__device__ __forceinline__ float tanha(float x) {
    float r; asm("tanh.approx.f32 %0, %1;" : "=f"(r) : "f"(x)); return r;
}
__device__ __forceinline__ float sigt(float x) {   // sigmoid via tanh
    return fmaf(0.5f, tanha(0.5f * x), 0.5f);
}
__device__ __forceinline__ __half2 u2h2(unsigned int u) {
    __half2 r; *reinterpret_cast<unsigned int*>(&r) = u; return r;
}
__device__ __forceinline__ unsigned h2u(__half2 h) {
    return *reinterpret_cast<unsigned*>(&h);
}
__device__ __forceinline__ void mma_f16(float* d, const unsigned* a, const unsigned* b) {
    asm volatile(
        "mma.sync.aligned.m16n8k16.row.col.f32.f16.f16.f32 "
        "{%0,%1,%2,%3},{%4,%5,%6,%7},{%8,%9},{%0,%1,%2,%3};"
        : "+f"(d[0]), "+f"(d[1]), "+f"(d[2]), "+f"(d[3])
        : "r"(a[0]), "r"(a[1]), "r"(a[2]), "r"(a[3]), "r"(b[0]), "r"(b[1]));
}

// ---------------------------------------------------------------------------
// fp16 tensor-core GEMM (fp32 accum): XPh[r][n] = A[r][:].W[n][:] + bias[n]
//   r = t*64+b;  AMODE 0: A=embeds (B,T,E) fp32, row r -> ((r&63)*512+(r>>6))*768
//                AMODE 1: A=g_H0h (row-major 256, fp16)
//   n<512 -> W0/bias0 (fwd), else W1/bias1 (rev)
// Tile BM=128, BN=128, BK=16; 8 warps (2m x 4n), warp tile 64x32.
// SMEM: half2 k2-major [k2][m], stride 136 (conflict-free frags), double buffer.
// ---------------------------------------------------------------------------
#define GBK 16
#define HSTR 136

template<int AMODE>
__global__ __launch_bounds__(256) void gemm_tc(
    const float* __restrict__ Aext, int Kdim,
    const float* __restrict__ W0, const float* __restrict__ W1,
    const float* __restrict__ bi0, const float* __restrict__ bh0,
    const float* __restrict__ bi1, const float* __restrict__ bh1)
{
    __shared__ unsigned As2[2][8 * HSTR];
    __shared__ unsigned Bs2[2][8 * HSTR];
    __shared__ float bias[128];

    const int tid  = threadIdx.x;
    const int lane = tid & 31, wid = tid >> 5;
    const int wm = wid >> 2, wn = wid & 3;        // 2 x 4 warp grid
    const int g = lane >> 2, tig = lane & 3;
    const int row0 = blockIdx.y * 128;
    const int col0 = blockIdx.x * 128;

    if (tid < 128) {
        int n = col0 + tid;
        bias[tid] = (n < 512) ? (bi0[n] + bh0[n]) : (bi1[n - 512] + bh1[n - 512]);
    }

    // global load mapping: per thread 8 values of A, 8 of B per 16-k tile
    const int arow = tid >> 1;             // 0..127
    const int ak   = (tid & 1) * 8;        // 0 or 8
    const int ak2  = ak >> 1;              // 0 or 4
    size_t aoff;
    {
        int r = row0 + arow;
        aoff = (AMODE == 0) ? ((size_t)(r & 63) * 512 + (size_t)(r >> 6)) * 768
                            : (size_t)r * 256;
    }
    const float* Af = Aext;
    const __half* Ah = g_H0h;
    const int nG = col0 + arow;
    const float* wrow = (nG < 512) ? (W0 + (size_t)nG * Kdim)
                                   : (W1 + (size_t)(nG - 512) * Kdim);

    float c[4][4][4];
#pragma unroll
    for (int i = 0; i < 4; i++)
#pragma unroll
        for (int j = 0; j < 4; j++)
#pragma unroll
            for (int q = 0; q < 4; q++) c[i][j][q] = 0.f;

    const int niter = Kdim / GBK;

    float4 av0, av1;     // AMODE 0
    uint4  au0;          // AMODE 1
    float4 bv0, bv1;

    // ---- prologue: tile 0 -> buf 0
    if (AMODE == 0) {
        av0 = *reinterpret_cast<const float4*>(Af + aoff + ak);
        av1 = *reinterpret_cast<const float4*>(Af + aoff + ak + 4);
    } else {
        au0 = *reinterpret_cast<const uint4*>(Ah + aoff + ak);
    }
    bv0 = *reinterpret_cast<const float4*>(wrow + ak);
    bv1 = *reinterpret_cast<const float4*>(wrow + ak + 4);

    if (AMODE == 0) {
        As2[0][(ak2 + 0) * HSTR + arow] = h2u(__floats2half2_rn(av0.x, av0.y));
        As2[0][(ak2 + 1) * HSTR + arow] = h2u(__floats2half2_rn(av0.z, av0.w));
        As2[0][(ak2 + 2) * HSTR + arow] = h2u(__floats2half2_rn(av1.x, av1.y));
        As2[0][(ak2 + 3) * HSTR + arow] = h2u(__floats2half2_rn(av1.z, av1.w));
    } else {
        As2[0][(ak2 + 0) * HSTR + arow] = au0.x;
        As2[0][(ak2 + 1) * HSTR + arow] = au0.y;
        As2[0][(ak2 + 2) * HSTR + arow] = au0.z;
        As2[0][(ak2 + 3) * HSTR + arow] = au0.w;
    }
    Bs2[0][(ak2 + 0) * HSTR + arow] = h2u(__floats2half2_rn(bv0.x, bv0.y));
    Bs2[0][(ak2 + 1) * HSTR + arow] = h2u(__floats2half2_rn(bv0.z, bv0.w));
    Bs2[0][(ak2 + 2) * HSTR + arow] = h2u(__floats2half2_rn(bv1.x, bv1.y));
    Bs2[0][(ak2 + 3) * HSTR + arow] = h2u(__floats2half2_rn(bv1.z, bv1.w));
    __syncthreads();

#pragma unroll 1
    for (int i = 0; i < niter; ++i) {
        const int pb = i & 1;
        if (i + 1 < niter) {
            const int k0 = (i + 1) * GBK;
            if (AMODE == 0) {
                av0 = *reinterpret_cast<const float4*>(Af + aoff + k0 + ak);
                av1 = *reinterpret_cast<const float4*>(Af + aoff + k0 + ak + 4);
            } else {
                au0 = *reinterpret_cast<const uint4*>(Ah + aoff + k0 + ak);
            }
            bv0 = *reinterpret_cast<const float4*>(wrow + k0 + ak);
            bv1 = *reinterpret_cast<const float4*>(wrow + k0 + ak + 4);
        }

        // compute tile i from buf pb
        {
            unsigned af[4][4], bf[4][2];
#pragma unroll
            for (int mt = 0; mt < 4; ++mt) {
                int m0 = wm * 64 + mt * 16;
                af[mt][0] = As2[pb][tig * HSTR + m0 + g];
                af[mt][1] = As2[pb][tig * HSTR + m0 + g + 8];
                af[mt][2] = As2[pb][(tig + 4) * HSTR + m0 + g];
                af[mt][3] = As2[pb][(tig + 4) * HSTR + m0 + g + 8];
            }
#pragma unroll
            for (int nt = 0; nt < 4; ++nt) {
                int n0 = wn * 32 + nt * 8;
                bf[nt][0] = Bs2[pb][tig * HSTR + n0 + g];
                bf[nt][1] = Bs2[pb][(tig + 4) * HSTR + n0 + g];
            }
#pragma unroll
            for (int mt = 0; mt < 4; ++mt)
#pragma unroll
                for (int nt = 0; nt < 4; ++nt)
                    mma_f16(c[mt][nt], af[mt], bf[nt]);
        }

        if (i + 1 < niter) {
            const int nb = pb ^ 1;
            if (AMODE == 0) {
                As2[nb][(ak2 + 0) * HSTR + arow] = h2u(__floats2half2_rn(av0.x, av0.y));
                As2[nb][(ak2 + 1) * HSTR + arow] = h2u(__floats2half2_rn(av0.z, av0.w));
                As2[nb][(ak2 + 2) * HSTR + arow] = h2u(__floats2half2_rn(av1.x, av1.y));
                As2[nb][(ak2 + 3) * HSTR + arow] = h2u(__floats2half2_rn(av1.z, av1.w));
            } else {
                As2[nb][(ak2 + 0) * HSTR + arow] = au0.x;
                As2[nb][(ak2 + 1) * HSTR + arow] = au0.y;
                As2[nb][(ak2 + 2) * HSTR + arow] = au0.z;
                As2[nb][(ak2 + 3) * HSTR + arow] = au0.w;
            }
            Bs2[nb][(ak2 + 0) * HSTR + arow] = h2u(__floats2half2_rn(bv0.x, bv0.y));
            Bs2[nb][(ak2 + 1) * HSTR + arow] = h2u(__floats2half2_rn(bv0.z, bv0.w));
            Bs2[nb][(ak2 + 2) * HSTR + arow] = h2u(__floats2half2_rn(bv1.x, bv1.y));
            Bs2[nb][(ak2 + 3) * HSTR + arow] = h2u(__floats2half2_rn(bv1.z, bv1.w));
        }
        __syncthreads();
    }

    // epilogue: XPh(row,col) = c + bias, packed half2
#pragma unroll
    for (int mt = 0; mt < 4; ++mt) {
#pragma unroll
        for (int nt = 0; nt < 4; ++nt) {
            int r  = row0 + wm * 64 + mt * 16 + g;
            int cb = wn * 32 + nt * 8 + 2 * tig;
            int col = col0 + cb;
            unsigned p0 = h2u(__floats2half2_rn(c[mt][nt][0] + bias[cb],
                                                c[mt][nt][1] + bias[cb + 1]));
            unsigned p1 = h2u(__floats2half2_rn(c[mt][nt][2] + bias[cb],
                                                c[mt][nt][3] + bias[cb + 1]));
            *reinterpret_cast<unsigned*>(&g_XPh[(size_t)r * 1024 + col]) = p0;
            *reinterpret_cast<unsigned*>(&g_XPh[(size_t)(r + 8) * 1024 + col]) = p1;
        }
    }
}

// ---------------------------------------------------------------------------
// LSTM recurrence: one block per (batch, dir). 512 threads = 16 warps.
// Warp w, lane l: hidden unit u = w*8 + (l&7), gate = l>>3.
// Weights in registers (fp16); h double-buffered in SMEM; tanh.approx
// activations pre-shfl; half-only xp combine; unroll-2 to fold buffer parity.
// ---------------------------------------------------------------------------
__global__ __launch_bounds__(512) void lstm_kernel(
    const float* __restrict__ whh_fwd, const float* __restrict__ whh_rev, int layer)
{
    __shared__ uint4 hbuf4[2][16];   // 2 x 128 halves

    const int b   = blockIdx.x >> 1;
    const int dir = blockIdx.x & 1;
    const float* whh = dir ? whh_rev : whh_fwd;

    const int lane = threadIdx.x & 31;
    const int wid  = threadIdx.x >> 5;
    const int u    = wid * 8 + (lane & 7);
    const int gate = lane >> 3;
    const int wrow_idx = gate * 128 + u;

    // weights -> registers (fp16)
    __half2 W[64];
    {
        const float4* wr4 = reinterpret_cast<const float4*>(whh + (size_t)wrow_idx * 128);
#pragma unroll
        for (int i = 0; i < 32; ++i) {
            float4 f = wr4[i];
            W[2 * i]     = __floats2half2_rn(f.x, f.y);
            W[2 * i + 1] = __floats2half2_rn(f.z, f.w);
        }
    }
    if (threadIdx.x < 16) hbuf4[0][threadIdx.x] = make_uint4(0u, 0u, 0u, 0u);
    float cst = 0.f;
    __syncthreads();

    const long xstride = dir ? -(long)(BB * 1024) : (long)(BB * 1024);
    const long hstride = dir ? -(long)(BB * 256)  : (long)(BB * 256);
    const size_t hbase = (size_t)(dir ? (TT - 1) : 0) * (BB * 256)
                       + (size_t)b * 256 + dir * 128 + u;
    const __half* xp_p = g_XPh + (size_t)(dir ? (TT - 1) : 0) * (BB * 1024)
                               + (size_t)b * 1024 + dir * 512 + wrow_idx;
    __half* hout_p = (layer ? g_H1h : g_H0h) + hbase;

    __half xp = *xp_p;

#pragma unroll 2
    for (int t = 0; t < TT; ++t) {
        // prefetch next step's xp (clamped pointer on last step)
        const __half* pf = xp_p + ((t < TT - 1) ? xstride : 0);
        __half xpn = *pf;

        const uint4* hb = hbuf4[t & 1];
        __half2 s0 = __floats2half2_rn(0.f, 0.f);
        __half2 s1 = s0, s2 = s0, s3 = s0;
#pragma unroll
        for (int k = 0; k < 4; ++k) {
            uint4 ha = hb[4 * k];
            uint4 hc = hb[4 * k + 1];
            uint4 hd = hb[4 * k + 2];
            uint4 he = hb[4 * k + 3];
            s0 = __hfma2(W[16 * k + 0],  u2h2(ha.x), s0);
            s1 = __hfma2(W[16 * k + 1],  u2h2(ha.y), s1);
            s2 = __hfma2(W[16 * k + 2],  u2h2(ha.z), s2);
            s3 = __hfma2(W[16 * k + 3],  u2h2(ha.w), s3);
            s0 = __hfma2(W[16 * k + 4],  u2h2(hc.x), s0);
            s1 = __hfma2(W[16 * k + 5],  u2h2(hc.y), s1);
            s2 = __hfma2(W[16 * k + 6],  u2h2(hc.z), s2);
            s3 = __hfma2(W[16 * k + 7],  u2h2(hc.w), s3);
            s0 = __hfma2(W[16 * k + 8],  u2h2(hd.x), s0);
            s1 = __hfma2(W[16 * k + 9],  u2h2(hd.y), s1);
            s2 = __hfma2(W[16 * k + 10], u2h2(hd.z), s2);
            s3 = __hfma2(W[16 * k + 11], u2h2(hd.w), s3);
            s0 = __hfma2(W[16 * k + 12], u2h2(he.x), s0);
            s1 = __hfma2(W[16 * k + 13], u2h2(he.y), s1);
            s2 = __hfma2(W[16 * k + 14], u2h2(he.z), s2);
            s3 = __hfma2(W[16 * k + 15], u2h2(he.w), s3);
        }
        // half-only combine: hadd2 tree -> lane sum -> + xp -> single F2F
        __half2 sh = __hadd2(__hadd2(s0, s1), __hadd2(s2, s3));
        __half  gh = __hadd(__hadd(__low2half(sh), __high2half(sh)), xp);
        const float gval = __half2float(gh);

        // activation by owning lane: tanh for gate 2, sigmoid (via tanh) else
        const float act = (gate == 2) ? tanha(gval) : sigt(gval);

        const int src = lane & 7;
        float iv = __shfl_sync(0xffffffffu, act, src);
        float fv = __shfl_sync(0xffffffffu, act, src + 8);
        float gv = __shfl_sync(0xffffffffu, act, src + 16);
        float ov = __shfl_sync(0xffffffffu, act, src + 24);

        if (lane < 8) {
            float cn = fv * cst + iv * gv;
            cst = cn;
            float hn = ov * tanha(cn);
            __half hcvt = __float2half_rn(hn);
            reinterpret_cast<__half*>(&hbuf4[(t & 1) ^ 1][0])[u] = hcvt;
            *hout_p = hcvt;
        }
        xp = xpn;
        xp_p += xstride;
        hout_p += hstride;
        __syncthreads();
    }
}

// ---------------------------------------------------------------------------
// CRF (fused emissions): one block per batch.
//  Phase 1: ems[t][n] = H1h[t*64+b][:] . lw[n][:] + lb[n]  (n<11, padded 12)
//  Phase 2: numerator (parallel over t); denominator (warp 0 forward algo,
//           baseline-rescaled LSE: exp(trans) hoisted, 2 MUFU/step)
// ---------------------------------------------------------------------------
__global__ __launch_bounds__(256) void crf_kernel(
    const int* __restrict__ tags, const void* __restrict__ maskraw,
    const float* __restrict__ start_t, const float* __restrict__ end_t,
    const float* __restrict__ trans,
    const float* __restrict__ lw, const float* __restrict__ lb)
{
    __shared__ float ems[TT * 12];
    __shared__ float redf[256];
    __shared__ int   redi[256];
    __shared__ unsigned char maskb[TT];
    __shared__ float s_num;

    const int b = blockIdx.x;
    const int tid = threadIdx.x;

    {
        const unsigned char* mc = reinterpret_cast<const unsigned char*>(maskraw);
        const bool bytewise = (mc[1] != 0);
        const int* mi = reinterpret_cast<const int*>(maskraw);
        for (int t = tid; t < TT; t += 256) {
            maskb[t] = bytewise ? (mc[(size_t)b * TT + t] != 0)
                                : (mi[(size_t)b * TT + t] != 0);
        }
    }

    // ---- fused emissions
    for (int base = tid; base < TT * 16; base += 256) {
        int t = base >> 4, n = base & 15;
        if (n < KK) {
            const uint4*  h4 = reinterpret_cast<const uint4*>(
                &g_H1h[((size_t)t * BB + b) * 256]);
            const float4* w4 = reinterpret_cast<const float4*>(lw + (size_t)n * 256);
            float acc = 0.f;
#pragma unroll 8
            for (int k = 0; k < 32; ++k) {
                uint4 hv = h4[k];
                float4 w0 = w4[2 * k], w1 = w4[2 * k + 1];
                float2 a0 = __half22float2(u2h2(hv.x));
                float2 a1 = __half22float2(u2h2(hv.y));
                float2 a2 = __half22float2(u2h2(hv.z));
                float2 a3 = __half22float2(u2h2(hv.w));
                acc += a0.x * w0.x + a0.y * w0.y + a1.x * w0.z + a1.y * w0.w;
                acc += a2.x * w1.x + a2.y * w1.y + a3.x * w1.z + a3.y * w1.w;
            }
            ems[t * 12 + n] = acc + lb[n];
        }
    }
    __syncthreads();

    // ---- numerator (parallel over t)
    float part = 0.f;
    int   cnt  = 0;
    for (int t = tid; t < TT; t += 256) cnt += maskb[t] ? 1 : 0;
    for (int t = 1 + tid; t < TT; t += 256) {
        if (maskb[t]) {
            int tp = tags[(size_t)b * TT + t - 1];
            int tc = tags[(size_t)b * TT + t];
            part += trans[tp * KK + tc] + ems[t * 12 + tc];
        }
    }
    redf[tid] = part; redi[tid] = cnt;
    __syncthreads();
    for (int s = 128; s > 0; s >>= 1) {
        if (tid < s) { redf[tid] += redf[tid + s]; redi[tid] += redi[tid + s]; }
        __syncthreads();
    }
    if (tid == 0) {
        int t0 = tags[(size_t)b * TT];
        int seqEnd = redi[0] - 1;
        s_num = start_t[t0] + ems[t0] + redf[0]
              + end_t[tags[(size_t)b * TT + seqEnd]];
    }
    __syncthreads();

    // ---- denominator (warp 0, baseline-rescaled forward algorithm)
    // LSE_i(score_i + T[i][j]) = m + ln( sum_i exp(score_i - m) * exp(T[i][j]) ),
    // with m = score_0 (any finite baseline is exact; spread is bounded).
    if (tid < 32) {
        const int lane = tid;
        float etcol[KK];   // exp(trans[i][lane]) — hoisted out of the time loop
        if (lane < KK) {
#pragma unroll
            for (int i = 0; i < KK; i++) etcol[i] = __expf(trans[i * KK + lane]);
        } else {
#pragma unroll
            for (int i = 0; i < KK; i++) etcol[i] = 0.f;
        }
        float score = (lane < KK) ? (start_t[lane] + ems[lane]) : -1e30f;

        for (int t = 1; t < TT; ++t) {
            if (maskb[t]) {
                float m = __shfl_sync(0xffffffffu, score, 0);
                float e = __expf(score - m);          // lanes >= KK -> 0
                float dot = 0.f;
#pragma unroll
                for (int i = 0; i < KK; i++)
                    dot = fmaf(__shfl_sync(0xffffffffu, e, i), etcol[i], dot);
                float nxt = m + __logf(dot) + ems[t * 12 + lane];
                if (lane < KK) score = nxt;
            }
        }
        float v = (lane < KK) ? (score + end_t[lane]) : -1e30f;
        float m = v;
#pragma unroll
        for (int off = 16; off > 0; off >>= 1)
            m = fmaxf(m, __shfl_xor_sync(0xffffffffu, m, off));
        float e = __expf(v - m);
#pragma unroll
        for (int off = 16; off > 0; off >>= 1)
            e += __shfl_xor_sync(0xffffffffu, e, off);
        float den = m + __logf(e);
        if (lane == 0) g_ND[b] = s_num - den;
    }
}

__global__ void finish_kernel(float* __restrict__ out, int out_n)
{
    __shared__ float s[64];
    int tid = threadIdx.x;
    s[tid] = g_ND[tid];
    __syncthreads();
    for (int st = 32; st > 0; st >>= 1) {
        if (tid < st) s[tid] += s[tid + st];
        __syncthreads();
    }
    if (tid == 0) out[0] = -s[0] / 64.f;
    if (tid > 0 && tid < out_n) out[tid] = 0.f;
}

// ---------------------------------------------------------------------------
extern "C" void kernel_launch(void* const* d_in, const int* in_sizes, int n_in,
                              void* d_out, int out_size)
{
    const float* embeds    = (const float*)d_in[0];
    const int*   tags      = (const int*)d_in[1];
    const void*  mask      = d_in[2];
    const float* w_ih_l0   = (const float*)d_in[3];
    const float* w_hh_l0   = (const float*)d_in[4];
    const float* b_ih_l0   = (const float*)d_in[5];
    const float* b_hh_l0   = (const float*)d_in[6];
    const float* w_ih_l0r  = (const float*)d_in[7];
    const float* w_hh_l0r  = (const float*)d_in[8];
    const float* b_ih_l0r  = (const float*)d_in[9];
    const float* b_hh_l0r  = (const float*)d_in[10];
    const float* w_ih_l1   = (const float*)d_in[11];
    const float* w_hh_l1   = (const float*)d_in[12];
    const float* b_ih_l1   = (const float*)d_in[13];
    const float* b_hh_l1   = (const float*)d_in[14];
    const float* w_ih_l1r  = (const float*)d_in[15];
    const float* w_hh_l1r  = (const float*)d_in[16];
    const float* b_ih_l1r  = (const float*)d_in[17];
    const float* b_hh_l1r  = (const float*)d_in[18];
    const float* linear_w  = (const float*)d_in[19];
    const float* linear_b  = (const float*)d_in[20];
    const float* start_tr  = (const float*)d_in[21];
    const float* end_tr    = (const float*)d_in[22];
    const float* trans     = (const float*)d_in[23];
    (void)in_sizes; (void)n_in;

    dim3 ggrid(8, 256);   // N/128 x M/128

    // layer 0
    gemm_tc<0><<<ggrid, 256>>>(embeds, 768,
                               w_ih_l0, w_ih_l0r, b_ih_l0, b_hh_l0, b_ih_l0r, b_hh_l0r);
    lstm_kernel<<<128, 512>>>(w_hh_l0, w_hh_l0r, 0);

    // layer 1 (A = g_H0h, fp16)
    gemm_tc<1><<<ggrid, 256>>>(nullptr, 256,
                               w_ih_l1, w_ih_l1r, b_ih_l1, b_hh_l1, b_ih_l1r, b_hh_l1r);
    lstm_kernel<<<128, 512>>>(w_hh_l1, w_hh_l1r, 1);

    // fused emissions + CRF
    crf_kernel<<<64, 256>>>(tags, mask, start_tr, end_tr, trans, linear_w, linear_b);
    finish_kernel<<<1, 64>>>((float*)d_out, out_size);
}

// round 10
// speedup vs baseline: 1.0861x; 1.0431x over previous
#include <cuda_runtime.h>
#include <cuda_fp16.h>
#include <cuda_bf16.h>

// Problem constants
#define BB 64
#define TT 512
#define EE 768
#define HH 128      // hidden per direction
#define KK 11

// ---------------------------------------------------------------------------
// Scratch (device globals; no dynamic allocation allowed)
// ---------------------------------------------------------------------------
__device__ __half g_XPh[(size_t)TT * BB * 1024];  // gate x-contributions (fp16)
__device__ __half g_Eh[(size_t)BB * TT * EE];     // embeds (fp16)
__device__ __half g_W0h[1024 * 768];              // [fwd;rev] w_ih layer0 (fp16)
__device__ __half g_W1h[1024 * 256];              // [fwd;rev] w_ih layer1 (fp16)
__device__ __half g_H0h[(size_t)TT * BB * 256];   // layer0 h (fp16, gemm1 A)
__device__ __half g_H1h[(size_t)TT * BB * 256];   // layer1 h (fp16, crf input)
__device__ float  g_ND[BB];                       // num - den per batch

__device__ __forceinline__ float tanha(float x) {
    float r; asm("tanh.approx.f32 %0, %1;" : "=f"(r) : "f"(x)); return r;
}
__device__ __forceinline__ float sigt(float x) {   // sigmoid via tanh
    return fmaf(0.5f, tanha(0.5f * x), 0.5f);
}
__device__ __forceinline__ __half2 u2h2(unsigned int u) {
    __half2 r; *reinterpret_cast<unsigned int*>(&r) = u; return r;
}
__device__ __forceinline__ unsigned h2u(__half2 h) {
    return *reinterpret_cast<unsigned*>(&h);
}
__device__ __forceinline__ void mma_f16(float* d, const unsigned* a, const unsigned* b) {
    asm volatile(
        "mma.sync.aligned.m16n8k16.row.col.f32.f16.f16.f32 "
        "{%0,%1,%2,%3},{%4,%5,%6,%7},{%8,%9},{%0,%1,%2,%3};"
        : "+f"(d[0]), "+f"(d[1]), "+f"(d[2]), "+f"(d[3])
        : "r"(a[0]), "r"(a[1]), "r"(a[2]), "r"(a[3]), "r"(b[0]), "r"(b[1]));
}

// ---------------------------------------------------------------------------
// fp32 -> fp16 conversion.  dst_id: 0 -> g_Eh, 1 -> g_W0h, 2 -> g_W1h
// ---------------------------------------------------------------------------
__global__ __launch_bounds__(256) void conv_f2h(
    const float* __restrict__ src, int n, int dst_id, int off)
{
    __half* dst = (dst_id == 0 ? g_Eh : dst_id == 1 ? g_W0h : g_W1h) + off;
    int i = (blockIdx.x * 256 + threadIdx.x) * 4;
    if (i < n) {
        float4 f = *reinterpret_cast<const float4*>(src + i);
        uint2 v;
        v.x = h2u(__floats2half2_rn(f.x, f.y));
        v.y = h2u(__floats2half2_rn(f.z, f.w));
        *reinterpret_cast<uint2*>(dst + i) = v;
    }
}

// ---------------------------------------------------------------------------
// fp16 tensor-core GEMM (fp32 accum): XPh[r][n] = A[r][:].W[n][:] + bias[n]
//   r = t*64+b;  AMODE 0: A=g_Eh (embeds layout: row r -> ((r&63)*512+(r>>6))*768)
//                AMODE 1: A=g_H0h (row-major 256)
//   W packed [fwd;rev] in g_W0h / g_W1h; bias n<512 fwd else rev.
// Tile BM=128, BN=128, BK=16; 8 warps (2m x 4n), warp tile 64x32.
// SMEM: half2 k2-major [k2][m], stride 136, double buffer. NO cvt in hot loop.
// ---------------------------------------------------------------------------
#define GBK 16
#define HSTR 136

template<int AMODE>
__global__ __launch_bounds__(256) void gemm_tc(
    int Kdim,
    const float* __restrict__ biF, const float* __restrict__ bhF,
    const float* __restrict__ biR, const float* __restrict__ bhR)
{
    __shared__ unsigned As2[2][8 * HSTR];
    __shared__ unsigned Bs2[2][8 * HSTR];
    __shared__ float bias[128];

    const int tid  = threadIdx.x;
    const int lane = tid & 31, wid = tid >> 5;
    const int wm = wid >> 2, wn = wid & 3;        // 2 x 4 warp grid
    const int g = lane >> 2, tig = lane & 3;
    const int row0 = blockIdx.y * 128;
    const int col0 = blockIdx.x * 128;

    if (tid < 128) {
        int n = col0 + tid;
        bias[tid] = (n < 512) ? (biF[n] + bhF[n]) : (biR[n - 512] + bhR[n - 512]);
    }

    // global load mapping: per thread 8 halves of A, 8 of B per 16-k tile
    const int arow = tid >> 1;             // 0..127
    const int ak   = (tid & 1) * 8;        // 0 or 8
    const int ak2  = ak >> 1;              // 0 or 4
    size_t aoff;
    {
        int r = row0 + arow;
        aoff = (AMODE == 0) ? ((size_t)(r & 63) * 512 + (size_t)(r >> 6)) * 768
                            : (size_t)r * 256;
    }
    const __half* Ah = (AMODE == 0) ? g_Eh : g_H0h;
    const __half* Wb = (AMODE == 0) ? g_W0h : g_W1h;
    const __half* wrow = Wb + (size_t)(col0 + arow) * Kdim;

    float c[4][4][4];
#pragma unroll
    for (int i = 0; i < 4; i++)
#pragma unroll
        for (int j = 0; j < 4; j++)
#pragma unroll
            for (int q = 0; q < 4; q++) c[i][j][q] = 0.f;

    const int niter = Kdim / GBK;
    uint4 au, bu;

    // ---- prologue: tile 0 -> buf 0
    au = *reinterpret_cast<const uint4*>(Ah + aoff + ak);
    bu = *reinterpret_cast<const uint4*>(wrow + ak);
    As2[0][(ak2 + 0) * HSTR + arow] = au.x;
    As2[0][(ak2 + 1) * HSTR + arow] = au.y;
    As2[0][(ak2 + 2) * HSTR + arow] = au.z;
    As2[0][(ak2 + 3) * HSTR + arow] = au.w;
    Bs2[0][(ak2 + 0) * HSTR + arow] = bu.x;
    Bs2[0][(ak2 + 1) * HSTR + arow] = bu.y;
    Bs2[0][(ak2 + 2) * HSTR + arow] = bu.z;
    Bs2[0][(ak2 + 3) * HSTR + arow] = bu.w;
    __syncthreads();

#pragma unroll 1
    for (int i = 0; i < niter; ++i) {
        const int pb = i & 1;
        if (i + 1 < niter) {
            const int k0 = (i + 1) * GBK;
            au = *reinterpret_cast<const uint4*>(Ah + aoff + k0 + ak);
            bu = *reinterpret_cast<const uint4*>(wrow + k0 + ak);
        }

        // compute tile i from buf pb
        {
            unsigned af[4][4], bf[4][2];
#pragma unroll
            for (int mt = 0; mt < 4; ++mt) {
                int m0 = wm * 64 + mt * 16;
                af[mt][0] = As2[pb][tig * HSTR + m0 + g];
                af[mt][1] = As2[pb][tig * HSTR + m0 + g + 8];
                af[mt][2] = As2[pb][(tig + 4) * HSTR + m0 + g];
                af[mt][3] = As2[pb][(tig + 4) * HSTR + m0 + g + 8];
            }
#pragma unroll
            for (int nt = 0; nt < 4; ++nt) {
                int n0 = wn * 32 + nt * 8;
                bf[nt][0] = Bs2[pb][tig * HSTR + n0 + g];
                bf[nt][1] = Bs2[pb][(tig + 4) * HSTR + n0 + g];
            }
#pragma unroll
            for (int mt = 0; mt < 4; ++mt)
#pragma unroll
                for (int nt = 0; nt < 4; ++nt)
                    mma_f16(c[mt][nt], af[mt], bf[nt]);
        }

        if (i + 1 < niter) {
            const int nb = pb ^ 1;
            As2[nb][(ak2 + 0) * HSTR + arow] = au.x;
            As2[nb][(ak2 + 1) * HSTR + arow] = au.y;
            As2[nb][(ak2 + 2) * HSTR + arow] = au.z;
            As2[nb][(ak2 + 3) * HSTR + arow] = au.w;
            Bs2[nb][(ak2 + 0) * HSTR + arow] = bu.x;
            Bs2[nb][(ak2 + 1) * HSTR + arow] = bu.y;
            Bs2[nb][(ak2 + 2) * HSTR + arow] = bu.z;
            Bs2[nb][(ak2 + 3) * HSTR + arow] = bu.w;
        }
        __syncthreads();
    }

    // epilogue: XPh(row,col) = c + bias, packed half2
#pragma unroll
    for (int mt = 0; mt < 4; ++mt) {
#pragma unroll
        for (int nt = 0; nt < 4; ++nt) {
            int r  = row0 + wm * 64 + mt * 16 + g;
            int cb = wn * 32 + nt * 8 + 2 * tig;
            int col = col0 + cb;
            unsigned p0 = h2u(__floats2half2_rn(c[mt][nt][0] + bias[cb],
                                                c[mt][nt][1] + bias[cb + 1]));
            unsigned p1 = h2u(__floats2half2_rn(c[mt][nt][2] + bias[cb],
                                                c[mt][nt][3] + bias[cb + 1]));
            *reinterpret_cast<unsigned*>(&g_XPh[(size_t)r * 1024 + col]) = p0;
            *reinterpret_cast<unsigned*>(&g_XPh[(size_t)(r + 8) * 1024 + col]) = p1;
        }
    }
}

// ---------------------------------------------------------------------------
// LSTM recurrence: one block per (batch, dir). 512 threads = 16 warps.
// Warp w, lane l: hidden unit u = w*8 + (l&7), gate = l>>3.
// Weights in registers (fp16); h double-buffered in SMEM; tanh.approx
// activations pre-shfl; half-only xp combine; unroll-2 folds buffer parity.
// ---------------------------------------------------------------------------
__global__ __launch_bounds__(512) void lstm_kernel(
    const float* __restrict__ whh_fwd, const float* __restrict__ whh_rev, int layer)
{
    __shared__ uint4 hbuf4[2][16];   // 2 x 128 halves

    const int b   = blockIdx.x >> 1;
    const int dir = blockIdx.x & 1;
    const float* whh = dir ? whh_rev : whh_fwd;

    const int lane = threadIdx.x & 31;
    const int wid  = threadIdx.x >> 5;
    const int u    = wid * 8 + (lane & 7);
    const int gate = lane >> 3;
    const int wrow_idx = gate * 128 + u;

    // weights -> registers (fp16)
    __half2 W[64];
    {
        const float4* wr4 = reinterpret_cast<const float4*>(whh + (size_t)wrow_idx * 128);
#pragma unroll
        for (int i = 0; i < 32; ++i) {
            float4 f = wr4[i];
            W[2 * i]     = __floats2half2_rn(f.x, f.y);
            W[2 * i + 1] = __floats2half2_rn(f.z, f.w);
        }
    }
    if (threadIdx.x < 16) hbuf4[0][threadIdx.x] = make_uint4(0u, 0u, 0u, 0u);
    float cst = 0.f;
    __syncthreads();

    const long xstride = dir ? -(long)(BB * 1024) : (long)(BB * 1024);
    const long hstride = dir ? -(long)(BB * 256)  : (long)(BB * 256);
    const size_t hbase = (size_t)(dir ? (TT - 1) : 0) * (BB * 256)
                       + (size_t)b * 256 + dir * 128 + u;
    const __half* xp_p = g_XPh + (size_t)(dir ? (TT - 1) : 0) * (BB * 1024)
                               + (size_t)b * 1024 + dir * 512 + wrow_idx;
    __half* hout_p = (layer ? g_H1h : g_H0h) + hbase;

    __half xp = *xp_p;

#pragma unroll 2
    for (int t = 0; t < TT; ++t) {
        // prefetch next step's xp (clamped pointer on last step)
        const __half* pf = xp_p + ((t < TT - 1) ? xstride : 0);
        __half xpn = *pf;

        const uint4* hb = hbuf4[t & 1];
        __half2 s0 = __floats2half2_rn(0.f, 0.f);
        __half2 s1 = s0, s2 = s0, s3 = s0;
#pragma unroll
        for (int k = 0; k < 4; ++k) {
            uint4 ha = hb[4 * k];
            uint4 hc = hb[4 * k + 1];
            uint4 hd = hb[4 * k + 2];
            uint4 he = hb[4 * k + 3];
            s0 = __hfma2(W[16 * k + 0],  u2h2(ha.x), s0);
            s1 = __hfma2(W[16 * k + 1],  u2h2(ha.y), s1);
            s2 = __hfma2(W[16 * k + 2],  u2h2(ha.z), s2);
            s3 = __hfma2(W[16 * k + 3],  u2h2(ha.w), s3);
            s0 = __hfma2(W[16 * k + 4],  u2h2(hc.x), s0);
            s1 = __hfma2(W[16 * k + 5],  u2h2(hc.y), s1);
            s2 = __hfma2(W[16 * k + 6],  u2h2(hc.z), s2);
            s3 = __hfma2(W[16 * k + 7],  u2h2(hc.w), s3);
            s0 = __hfma2(W[16 * k + 8],  u2h2(hd.x), s0);
            s1 = __hfma2(W[16 * k + 9],  u2h2(hd.y), s1);
            s2 = __hfma2(W[16 * k + 10], u2h2(hd.z), s2);
            s3 = __hfma2(W[16 * k + 11], u2h2(hd.w), s3);
            s0 = __hfma2(W[16 * k + 12], u2h2(he.x), s0);
            s1 = __hfma2(W[16 * k + 13], u2h2(he.y), s1);
            s2 = __hfma2(W[16 * k + 14], u2h2(he.z), s2);
            s3 = __hfma2(W[16 * k + 15], u2h2(he.w), s3);
        }
        // half-only combine: hadd2 tree -> lane sum -> + xp -> single F2F
        __half2 sh = __hadd2(__hadd2(s0, s1), __hadd2(s2, s3));
        __half  gh = __hadd(__hadd(__low2half(sh), __high2half(sh)), xp);
        const float gval = __half2float(gh);

        // activation by owning lane: tanh for gate 2, sigmoid (via tanh) else
        const float act = (gate == 2) ? tanha(gval) : sigt(gval);

        const int src = lane & 7;
        float iv = __shfl_sync(0xffffffffu, act, src);
        float fv = __shfl_sync(0xffffffffu, act, src + 8);
        float gv = __shfl_sync(0xffffffffu, act, src + 16);
        float ov = __shfl_sync(0xffffffffu, act, src + 24);

        if (lane < 8) {
            float cn = fv * cst + iv * gv;
            cst = cn;
            float hn = ov * tanha(cn);
            __half hcvt = __float2half_rn(hn);
            reinterpret_cast<__half*>(&hbuf4[(t & 1) ^ 1][0])[u] = hcvt;
            *hout_p = hcvt;
        }
        xp = xpn;
        xp_p += xstride;
        hout_p += hstride;
        __syncthreads();
    }
}

// ---------------------------------------------------------------------------
// CRF (fused emissions): one block per batch.
// ---------------------------------------------------------------------------
__global__ __launch_bounds__(256) void crf_kernel(
    const int* __restrict__ tags, const void* __restrict__ maskraw,
    const float* __restrict__ start_t, const float* __restrict__ end_t,
    const float* __restrict__ trans,
    const float* __restrict__ lw, const float* __restrict__ lb)
{
    __shared__ float ems[TT * 12];
    __shared__ float redf[256];
    __shared__ int   redi[256];
    __shared__ unsigned char maskb[TT];
    __shared__ float s_num;

    const int b = blockIdx.x;
    const int tid = threadIdx.x;

    {
        const unsigned char* mc = reinterpret_cast<const unsigned char*>(maskraw);
        const bool bytewise = (mc[1] != 0);
        const int* mi = reinterpret_cast<const int*>(maskraw);
        for (int t = tid; t < TT; t += 256) {
            maskb[t] = bytewise ? (mc[(size_t)b * TT + t] != 0)
                                : (mi[(size_t)b * TT + t] != 0);
        }
    }

    // ---- fused emissions
    for (int base = tid; base < TT * 16; base += 256) {
        int t = base >> 4, n = base & 15;
        if (n < KK) {
            const uint4*  h4 = reinterpret_cast<const uint4*>(
                &g_H1h[((size_t)t * BB + b) * 256]);
            const float4* w4 = reinterpret_cast<const float4*>(lw + (size_t)n * 256);
            float acc = 0.f;
#pragma unroll 8
            for (int k = 0; k < 32; ++k) {
                uint4 hv = h4[k];
                float4 w0 = w4[2 * k], w1 = w4[2 * k + 1];
                float2 a0 = __half22float2(u2h2(hv.x));
                float2 a1 = __half22float2(u2h2(hv.y));
                float2 a2 = __half22float2(u2h2(hv.z));
                float2 a3 = __half22float2(u2h2(hv.w));
                acc += a0.x * w0.x + a0.y * w0.y + a1.x * w0.z + a1.y * w0.w;
                acc += a2.x * w1.x + a2.y * w1.y + a3.x * w1.z + a3.y * w1.w;
            }
            ems[t * 12 + n] = acc + lb[n];
        }
    }
    __syncthreads();

    // ---- numerator (parallel over t)
    float part = 0.f;
    int   cnt  = 0;
    for (int t = tid; t < TT; t += 256) cnt += maskb[t] ? 1 : 0;
    for (int t = 1 + tid; t < TT; t += 256) {
        if (maskb[t]) {
            int tp = tags[(size_t)b * TT + t - 1];
            int tc = tags[(size_t)b * TT + t];
            part += trans[tp * KK + tc] + ems[t * 12 + tc];
        }
    }
    redf[tid] = part; redi[tid] = cnt;
    __syncthreads();
    for (int s = 128; s > 0; s >>= 1) {
        if (tid < s) { redf[tid] += redf[tid + s]; redi[tid] += redi[tid + s]; }
        __syncthreads();
    }
    if (tid == 0) {
        int t0 = tags[(size_t)b * TT];
        int seqEnd = redi[0] - 1;
        s_num = start_t[t0] + ems[t0] + redf[0]
              + end_t[tags[(size_t)b * TT + seqEnd]];
    }
    __syncthreads();

    // ---- denominator (warp 0, baseline-rescaled forward algorithm)
    if (tid < 32) {
        const int lane = tid;
        float etcol[KK];   // exp(trans[i][lane]) — hoisted
        if (lane < KK) {
#pragma unroll
            for (int i = 0; i < KK; i++) etcol[i] = __expf(trans[i * KK + lane]);
        } else {
#pragma unroll
            for (int i = 0; i < KK; i++) etcol[i] = 0.f;
        }
        float score = (lane < KK) ? (start_t[lane] + ems[lane]) : -1e30f;

        for (int t = 1; t < TT; ++t) {
            if (maskb[t]) {
                float m = __shfl_sync(0xffffffffu, score, 0);
                float e = __expf(score - m);
                float dot = 0.f;
#pragma unroll
                for (int i = 0; i < KK; i++)
                    dot = fmaf(__shfl_sync(0xffffffffu, e, i), etcol[i], dot);
                float nxt = m + __logf(dot) + ems[t * 12 + lane];
                if (lane < KK) score = nxt;
            }
        }
        float v = (lane < KK) ? (score + end_t[lane]) : -1e30f;
        float m = v;
#pragma unroll
        for (int off = 16; off > 0; off >>= 1)
            m = fmaxf(m, __shfl_xor_sync(0xffffffffu, m, off));
        float e = __expf(v - m);
#pragma unroll
        for (int off = 16; off > 0; off >>= 1)
            e += __shfl_xor_sync(0xffffffffu, e, off);
        float den = m + __logf(e);
        if (lane == 0) g_ND[b] = s_num - den;
    }
}

__global__ void finish_kernel(float* __restrict__ out, int out_n)
{
    __shared__ float s[64];
    int tid = threadIdx.x;
    s[tid] = g_ND[tid];
    __syncthreads();
    for (int st = 32; st > 0; st >>= 1) {
        if (tid < st) s[tid] += s[tid + st];
        __syncthreads();
    }
    if (tid == 0) out[0] = -s[0] / 64.f;
    if (tid > 0 && tid < out_n) out[tid] = 0.f;
}

// ---------------------------------------------------------------------------
extern "C" void kernel_launch(void* const* d_in, const int* in_sizes, int n_in,
                              void* d_out, int out_size)
{
    const float* embeds    = (const float*)d_in[0];
    const int*   tags      = (const int*)d_in[1];
    const void*  mask      = d_in[2];
    const float* w_ih_l0   = (const float*)d_in[3];
    const float* w_hh_l0   = (const float*)d_in[4];
    const float* b_ih_l0   = (const float*)d_in[5];
    const float* b_hh_l0   = (const float*)d_in[6];
    const float* w_ih_l0r  = (const float*)d_in[7];
    const float* w_hh_l0r  = (const float*)d_in[8];
    const float* b_ih_l0r  = (const float*)d_in[9];
    const float* b_hh_l0r  = (const float*)d_in[10];
    const float* w_ih_l1   = (const float*)d_in[11];
    const float* w_hh_l1   = (const float*)d_in[12];
    const float* b_ih_l1   = (const float*)d_in[13];
    const float* b_hh_l1   = (const float*)d_in[14];
    const float* w_ih_l1r  = (const float*)d_in[15];
    const float* w_hh_l1r  = (const float*)d_in[16];
    const float* b_ih_l1r  = (const float*)d_in[17];
    const float* b_hh_l1r  = (const float*)d_in[18];
    const float* linear_w  = (const float*)d_in[19];
    const float* linear_b  = (const float*)d_in[20];
    const float* start_tr  = (const float*)d_in[21];
    const float* end_tr    = (const float*)d_in[22];
    const float* trans     = (const float*)d_in[23];
    (void)in_sizes; (void)n_in;

    // ---- one-time fp16 conversions (embeds + packed w_ih weights)
    conv_f2h<<<(BB * TT * EE / 4 + 255) / 256, 256>>>(embeds, BB * TT * EE, 0, 0);
    conv_f2h<<<(512 * 768 / 4 + 255) / 256, 256>>>(w_ih_l0,  512 * 768, 1, 0);
    conv_f2h<<<(512 * 768 / 4 + 255) / 256, 256>>>(w_ih_l0r, 512 * 768, 1, 512 * 768);
    conv_f2h<<<(512 * 256 / 4 + 255) / 256, 256>>>(w_ih_l1,  512 * 256, 2, 0);
    conv_f2h<<<(512 * 256 / 4 + 255) / 256, 256>>>(w_ih_l1r, 512 * 256, 2, 512 * 256);

    dim3 ggrid(8, 256);   // N/128 x M/128

    // layer 0
    gemm_tc<0><<<ggrid, 256>>>(768, b_ih_l0, b_hh_l0, b_ih_l0r, b_hh_l0r);
    lstm_kernel<<<128, 512>>>(w_hh_l0, w_hh_l0r, 0);

    // layer 1 (A = g_H0h)
    gemm_tc<1><<<ggrid, 256>>>(256, b_ih_l1, b_hh_l1, b_ih_l1r, b_hh_l1r);
    lstm_kernel<<<128, 512>>>(w_hh_l1, w_hh_l1r, 1);

    // fused emissions + CRF
    crf_kernel<<<64, 256>>>(tags, mask, start_tr, end_tr, trans, linear_w, linear_b);
    finish_kernel<<<1, 64>>>((float*)d_out, out_size);
}

// round 12
// speedup vs baseline: 1.1556x; 1.0639x over previous
#include <cuda_runtime.h>
#include <cuda_fp16.h>
#include <cuda_bf16.h>
#include <cstdint>

// Problem constants
#define BB 64
#define TT 512
#define EE 768
#define HH 128      // hidden per direction
#define KK 11

// ---------------------------------------------------------------------------
// Scratch (device globals; no dynamic allocation allowed)
// ---------------------------------------------------------------------------
__device__ __half g_XPh[(size_t)TT * BB * 1024];  // gate x-contributions (fp16)
__device__ __half g_Eh[(size_t)BB * TT * EE];     // embeds (fp16)
__device__ __half g_W0h[1024 * 768];              // [fwd;rev] w_ih layer0 (fp16)
__device__ __half g_W1h[1024 * 256];              // [fwd;rev] w_ih layer1 (fp16)
__device__ __half g_H0h[(size_t)TT * BB * 256];   // layer0 h (fp16, gemm1 A)
__device__ __half g_H1h[(size_t)TT * BB * 256];   // layer1 h (fp16, crf input)
__device__ float  g_ND[BB];                       // num - den per batch

__device__ __forceinline__ float tanha(float x) {
    float r; asm("tanh.approx.f32 %0, %1;" : "=f"(r) : "f"(x)); return r;
}
__device__ __forceinline__ float sigt(float x) {   // sigmoid via tanh
    return fmaf(0.5f, tanha(0.5f * x), 0.5f);
}
__device__ __forceinline__ __half2 u2h2(unsigned int u) {
    __half2 r; *reinterpret_cast<unsigned int*>(&r) = u; return r;
}
__device__ __forceinline__ unsigned h2u(__half2 h) {
    return *reinterpret_cast<unsigned*>(&h);
}
__device__ __forceinline__ void mma_f16(float* d, const unsigned* a, const unsigned* b) {
    asm volatile(
        "mma.sync.aligned.m16n8k16.row.col.f32.f16.f16.f32 "
        "{%0,%1,%2,%3},{%4,%5,%6,%7},{%8,%9},{%0,%1,%2,%3};"
        : "+f"(d[0]), "+f"(d[1]), "+f"(d[2]), "+f"(d[3])
        : "r"(a[0]), "r"(a[1]), "r"(a[2]), "r"(a[3]), "r"(b[0]), "r"(b[1]));
}
__device__ __forceinline__ unsigned smem_u32(const void* p) {
    unsigned a;
    asm("{ .reg .u64 t; cvta.to.shared.u64 t, %1; cvt.u32.u64 %0, t; }"
        : "=r"(a) : "l"(p));
    return a;
}
__device__ __forceinline__ void ldsm_x4(unsigned& r0, unsigned& r1,
                                        unsigned& r2, unsigned& r3, unsigned addr) {
    asm volatile("ldmatrix.sync.aligned.m8n8.x4.shared.b16 {%0,%1,%2,%3}, [%4];"
                 : "=r"(r0), "=r"(r1), "=r"(r2), "=r"(r3) : "r"(addr));
}

// ---------------------------------------------------------------------------
// fp32 -> fp16 conversion.  dst_id: 0 -> g_Eh, 1 -> g_W0h, 2 -> g_W1h
// ---------------------------------------------------------------------------
__global__ __launch_bounds__(256) void conv_f2h(
    const float* __restrict__ src, int n, int dst_id, int off)
{
    __half* dst = (dst_id == 0 ? g_Eh : dst_id == 1 ? g_W0h : g_W1h) + off;
    int i = (blockIdx.x * 256 + threadIdx.x) * 4;
    if (i < n) {
        float4 f = *reinterpret_cast<const float4*>(src + i);
        uint2 v;
        v.x = h2u(__floats2half2_rn(f.x, f.y));
        v.y = h2u(__floats2half2_rn(f.z, f.w));
        *reinterpret_cast<uint2*>(dst + i) = v;
    }
}

// ---------------------------------------------------------------------------
// fp16 tensor-core GEMM (fp32 accum) with ldmatrix fragment loads.
//   XPh[r][n] = A[r][:].W[n][:] + bias[n]
//   AMODE 0: A=g_Eh (embeds layout: row r -> ((r&63)*512+(r>>6))*768), W=g_W0h
//   AMODE 1: A=g_H0h (row-major 256), W=g_W1h
// Tile BM=128, BN=128, BK=16; 8 warps (2m x 4n), warp tile 64x32.
// SMEM: row-major [row][16 halves] (32B rows), chunk swizzle c^=((row>>2)&1);
// double buffer. Per warp/tile: 2 STS.128 + 6 LDSM.x4 + 16 HMMA.
// ---------------------------------------------------------------------------
#define GBK 16

template<int AMODE>
__global__ __launch_bounds__(256) void gemm_tc(
    int Kdim,
    const float* __restrict__ biF, const float* __restrict__ bhF,
    const float* __restrict__ biR, const float* __restrict__ bhR)
{
    __shared__ __half As[2][128 * 16];
    __shared__ __half Bs[2][128 * 16];
    __shared__ float bias[128];

    const int tid  = threadIdx.x;
    const int lane = tid & 31, wid = tid >> 5;
    const int wm = wid >> 2, wn = wid & 3;        // 2 x 4 warp grid
    const int g = lane >> 2, tig = lane & 3;
    const int row0 = blockIdx.y * 128;
    const int col0 = blockIdx.x * 128;

    if (tid < 128) {
        int n = col0 + tid;
        bias[tid] = (n < 512) ? (biF[n] + bhF[n]) : (biR[n - 512] + bhR[n - 512]);
    }

    // ---- global load mapping: per thread 8 halves of A, 8 of B per 16-k tile
    const int arow = tid >> 1;             // 0..127
    const int ak   = (tid & 1) * 8;        // 0 or 8 (k-half offset)
    size_t aoff;
    {
        int r = row0 + arow;
        aoff = (AMODE == 0) ? ((size_t)(r & 63) * 512 + (size_t)(r >> 6)) * 768
                            : (size_t)r * 256;
    }
    const __half* Ah = (AMODE == 0) ? g_Eh : g_H0h;
    const __half* Wb = (AMODE == 0) ? g_W0h : g_W1h;
    const __half* wrow = Wb + (size_t)(col0 + arow) * Kdim;

    // ---- swizzled STS index (halves): row*16 + (chunk ^ ((row>>2)&1))*8
    const int schunk = (ak >> 3) ^ ((arow >> 2) & 1);
    const int sIdx = arow * 16 + schunk * 8;

    // ---- ldmatrix per-thread byte offsets (constant across iterations)
    // A frag (m16 x k16), mt = 0..3:
    //   row = m0 + (lane&7) + ((lane>>3)&1)*8, chunk = (lane>>4)&1
    unsigned offA[4];
#pragma unroll
    for (int mt = 0; mt < 4; ++mt) {
        int row = wm * 64 + mt * 16 + (lane & 7) + ((lane >> 3) & 1) * 8;
        int ch  = ((lane >> 4) & 1) ^ ((row >> 2) & 1);
        offA[mt] = (unsigned)(row * 32 + ch * 16);
    }
    // B frags: pair p covers n-tiles 2p, 2p+1:
    //   row = wn*32 + p*16 + ((lane>>4)&1)*8 + (lane&7), chunk = (lane>>3)&1
    unsigned offB[2];
#pragma unroll
    for (int p = 0; p < 2; ++p) {
        int row = wn * 32 + p * 16 + ((lane >> 4) & 1) * 8 + (lane & 7);
        int ch  = ((lane >> 3) & 1) ^ ((row >> 2) & 1);
        offB[p] = (unsigned)(row * 32 + ch * 16);
    }
    const unsigned baseA[2] = { smem_u32(As[0]), smem_u32(As[1]) };
    const unsigned baseB[2] = { smem_u32(Bs[0]), smem_u32(Bs[1]) };

    float c[4][4][4];
#pragma unroll
    for (int i = 0; i < 4; i++)
#pragma unroll
        for (int j = 0; j < 4; j++)
#pragma unroll
            for (int q = 0; q < 4; q++) c[i][j][q] = 0.f;

    const int niter = Kdim / GBK;
    uint4 au, bu;

    // ---- prologue: tile 0 -> buf 0
    au = *reinterpret_cast<const uint4*>(Ah + aoff + ak);
    bu = *reinterpret_cast<const uint4*>(wrow + ak);
    *reinterpret_cast<uint4*>(&As[0][sIdx]) = au;
    *reinterpret_cast<uint4*>(&Bs[0][sIdx]) = bu;
    __syncthreads();

#pragma unroll 1
    for (int i = 0; i < niter; ++i) {
        const int pb = i & 1;
        if (i + 1 < niter) {
            const int k0 = (i + 1) * GBK;
            au = *reinterpret_cast<const uint4*>(Ah + aoff + k0 + ak);
            bu = *reinterpret_cast<const uint4*>(wrow + k0 + ak);
        }

        // fragments via ldmatrix from buf pb
        {
            unsigned af[4][4], bf[4][2];
#pragma unroll
            for (int mt = 0; mt < 4; ++mt)
                ldsm_x4(af[mt][0], af[mt][1], af[mt][2], af[mt][3],
                        baseA[pb] + offA[mt]);
#pragma unroll
            for (int p = 0; p < 2; ++p)
                ldsm_x4(bf[2 * p][0], bf[2 * p][1], bf[2 * p + 1][0], bf[2 * p + 1][1],
                        baseB[pb] + offB[p]);
#pragma unroll
            for (int mt = 0; mt < 4; ++mt)
#pragma unroll
                for (int nt = 0; nt < 4; ++nt)
                    mma_f16(c[mt][nt], af[mt], bf[nt]);
        }

        if (i + 1 < niter) {
            const int nb = pb ^ 1;
            *reinterpret_cast<uint4*>(&As[nb][sIdx]) = au;
            *reinterpret_cast<uint4*>(&Bs[nb][sIdx]) = bu;
        }
        __syncthreads();
    }

    // epilogue: XPh(row,col) = c + bias, packed half2
#pragma unroll
    for (int mt = 0; mt < 4; ++mt) {
#pragma unroll
        for (int nt = 0; nt < 4; ++nt) {
            int r  = row0 + wm * 64 + mt * 16 + g;
            int cb = wn * 32 + nt * 8 + 2 * tig;
            int col = col0 + cb;
            unsigned p0 = h2u(__floats2half2_rn(c[mt][nt][0] + bias[cb],
                                                c[mt][nt][1] + bias[cb + 1]));
            unsigned p1 = h2u(__floats2half2_rn(c[mt][nt][2] + bias[cb],
                                                c[mt][nt][3] + bias[cb + 1]));
            *reinterpret_cast<unsigned*>(&g_XPh[(size_t)r * 1024 + col]) = p0;
            *reinterpret_cast<unsigned*>(&g_XPh[(size_t)(r + 8) * 1024 + col]) = p1;
        }
    }
}

// ---------------------------------------------------------------------------
// LSTM recurrence: one block per (batch, dir). 512 threads = 16 warps.
// (unchanged R10 config — measured best)
// ---------------------------------------------------------------------------
__global__ __launch_bounds__(512) void lstm_kernel(
    const float* __restrict__ whh_fwd, const float* __restrict__ whh_rev, int layer)
{
    __shared__ uint4 hbuf4[2][16];   // 2 x 128 halves

    const int b   = blockIdx.x >> 1;
    const int dir = blockIdx.x & 1;
    const float* whh = dir ? whh_rev : whh_fwd;

    const int lane = threadIdx.x & 31;
    const int wid  = threadIdx.x >> 5;
    const int u    = wid * 8 + (lane & 7);
    const int gate = lane >> 3;
    const int wrow_idx = gate * 128 + u;

    // weights -> registers (fp16)
    __half2 W[64];
    {
        const float4* wr4 = reinterpret_cast<const float4*>(whh + (size_t)wrow_idx * 128);
#pragma unroll
        for (int i = 0; i < 32; ++i) {
            float4 f = wr4[i];
            W[2 * i]     = __floats2half2_rn(f.x, f.y);
            W[2 * i + 1] = __floats2half2_rn(f.z, f.w);
        }
    }
    if (threadIdx.x < 16) hbuf4[0][threadIdx.x] = make_uint4(0u, 0u, 0u, 0u);
    float cst = 0.f;
    __syncthreads();

    const long xstride = dir ? -(long)(BB * 1024) : (long)(BB * 1024);
    const long hstride = dir ? -(long)(BB * 256)  : (long)(BB * 256);
    const size_t hbase = (size_t)(dir ? (TT - 1) : 0) * (BB * 256)
                       + (size_t)b * 256 + dir * 128 + u;
    const __half* xp_p = g_XPh + (size_t)(dir ? (TT - 1) : 0) * (BB * 1024)
                               + (size_t)b * 1024 + dir * 512 + wrow_idx;
    __half* hout_p = (layer ? g_H1h : g_H0h) + hbase;

    __half xp = *xp_p;

#pragma unroll 2
    for (int t = 0; t < TT; ++t) {
        const __half* pf = xp_p + ((t < TT - 1) ? xstride : 0);
        __half xpn = *pf;

        const uint4* hb = hbuf4[t & 1];
        __half2 s0 = __floats2half2_rn(0.f, 0.f);
        __half2 s1 = s0, s2 = s0, s3 = s0;
#pragma unroll
        for (int k = 0; k < 4; ++k) {
            uint4 ha = hb[4 * k];
            uint4 hc = hb[4 * k + 1];
            uint4 hd = hb[4 * k + 2];
            uint4 he = hb[4 * k + 3];
            s0 = __hfma2(W[16 * k + 0],  u2h2(ha.x), s0);
            s1 = __hfma2(W[16 * k + 1],  u2h2(ha.y), s1);
            s2 = __hfma2(W[16 * k + 2],  u2h2(ha.z), s2);
            s3 = __hfma2(W[16 * k + 3],  u2h2(ha.w), s3);
            s0 = __hfma2(W[16 * k + 4],  u2h2(hc.x), s0);
            s1 = __hfma2(W[16 * k + 5],  u2h2(hc.y), s1);
            s2 = __hfma2(W[16 * k + 6],  u2h2(hc.z), s2);
            s3 = __hfma2(W[16 * k + 7],  u2h2(hc.w), s3);
            s0 = __hfma2(W[16 * k + 8],  u2h2(hd.x), s0);
            s1 = __hfma2(W[16 * k + 9],  u2h2(hd.y), s1);
            s2 = __hfma2(W[16 * k + 10], u2h2(hd.z), s2);
            s3 = __hfma2(W[16 * k + 11], u2h2(hd.w), s3);
            s0 = __hfma2(W[16 * k + 12], u2h2(he.x), s0);
            s1 = __hfma2(W[16 * k + 13], u2h2(he.y), s1);
            s2 = __hfma2(W[16 * k + 14], u2h2(he.z), s2);
            s3 = __hfma2(W[16 * k + 15], u2h2(he.w), s3);
        }
        __half2 sh = __hadd2(__hadd2(s0, s1), __hadd2(s2, s3));
        __half  gh = __hadd(__hadd(__low2half(sh), __high2half(sh)), xp);
        const float gval = __half2float(gh);

        const float act = (gate == 2) ? tanha(gval) : sigt(gval);

        const int src = lane & 7;
        float iv = __shfl_sync(0xffffffffu, act, src);
        float fv = __shfl_sync(0xffffffffu, act, src + 8);
        float gv = __shfl_sync(0xffffffffu, act, src + 16);
        float ov = __shfl_sync(0xffffffffu, act, src + 24);

        if (lane < 8) {
            float cn = fv * cst + iv * gv;
            cst = cn;
            float hn = ov * tanha(cn);
            __half hcvt = __float2half_rn(hn);
            reinterpret_cast<__half*>(&hbuf4[(t & 1) ^ 1][0])[u] = hcvt;
            *hout_p = hcvt;
        }
        xp = xpn;
        xp_p += xstride;
        hout_p += hstride;
        __syncthreads();
    }
}

// ---------------------------------------------------------------------------
// CRF (fused emissions): one block per batch.  (unchanged R10)
// ---------------------------------------------------------------------------
__global__ __launch_bounds__(256) void crf_kernel(
    const int* __restrict__ tags, const void* __restrict__ maskraw,
    const float* __restrict__ start_t, const float* __restrict__ end_t,
    const float* __restrict__ trans,
    const float* __restrict__ lw, const float* __restrict__ lb)
{
    __shared__ float ems[TT * 12];
    __shared__ float redf[256];
    __shared__ int   redi[256];
    __shared__ unsigned char maskb[TT];
    __shared__ float s_num;

    const int b = blockIdx.x;
    const int tid = threadIdx.x;

    {
        const unsigned char* mc = reinterpret_cast<const unsigned char*>(maskraw);
        const bool bytewise = (mc[1] != 0);
        const int* mi = reinterpret_cast<const int*>(maskraw);
        for (int t = tid; t < TT; t += 256) {
            maskb[t] = bytewise ? (mc[(size_t)b * TT + t] != 0)
                                : (mi[(size_t)b * TT + t] != 0);
        }
    }

    // ---- fused emissions
    for (int base = tid; base < TT * 16; base += 256) {
        int t = base >> 4, n = base & 15;
        if (n < KK) {
            const uint4*  h4 = reinterpret_cast<const uint4*>(
                &g_H1h[((size_t)t * BB + b) * 256]);
            const float4* w4 = reinterpret_cast<const float4*>(lw + (size_t)n * 256);
            float acc = 0.f;
#pragma unroll 8
            for (int k = 0; k < 32; ++k) {
                uint4 hv = h4[k];
                float4 w0 = w4[2 * k], w1 = w4[2 * k + 1];
                float2 a0 = __half22float2(u2h2(hv.x));
                float2 a1 = __half22float2(u2h2(hv.y));
                float2 a2 = __half22float2(u2h2(hv.z));
                float2 a3 = __half22float2(u2h2(hv.w));
                acc += a0.x * w0.x + a0.y * w0.y + a1.x * w0.z + a1.y * w0.w;
                acc += a2.x * w1.x + a2.y * w1.y + a3.x * w1.z + a3.y * w1.w;
            }
            ems[t * 12 + n] = acc + lb[n];
        }
    }
    __syncthreads();

    // ---- numerator (parallel over t)
    float part = 0.f;
    int   cnt  = 0;
    for (int t = tid; t < TT; t += 256) cnt += maskb[t] ? 1 : 0;
    for (int t = 1 + tid; t < TT; t += 256) {
        if (maskb[t]) {
            int tp = tags[(size_t)b * TT + t - 1];
            int tc = tags[(size_t)b * TT + t];
            part += trans[tp * KK + tc] + ems[t * 12 + tc];
        }
    }
    redf[tid] = part; redi[tid] = cnt;
    __syncthreads();
    for (int s = 128; s > 0; s >>= 1) {
        if (tid < s) { redf[tid] += redf[tid + s]; redi[tid] += redi[tid + s]; }
        __syncthreads();
    }
    if (tid == 0) {
        int t0 = tags[(size_t)b * TT];
        int seqEnd = redi[0] - 1;
        s_num = start_t[t0] + ems[t0] + redf[0]
              + end_t[tags[(size_t)b * TT + seqEnd]];
    }
    __syncthreads();

    // ---- denominator (warp 0, baseline-rescaled forward algorithm)
    if (tid < 32) {
        const int lane = tid;
        float etcol[KK];
        if (lane < KK) {
#pragma unroll
            for (int i = 0; i < KK; i++) etcol[i] = __expf(trans[i * KK + lane]);
        } else {
#pragma unroll
            for (int i = 0; i < KK; i++) etcol[i] = 0.f;
        }
        float score = (lane < KK) ? (start_t[lane] + ems[lane]) : -1e30f;

        for (int t = 1; t < TT; ++t) {
            if (maskb[t]) {
                float m = __shfl_sync(0xffffffffu, score, 0);
                float e = __expf(score - m);
                float dot = 0.f;
#pragma unroll
                for (int i = 0; i < KK; i++)
                    dot = fmaf(__shfl_sync(0xffffffffu, e, i), etcol[i], dot);
                float nxt = m + __logf(dot) + ems[t * 12 + lane];
                if (lane < KK) score = nxt;
            }
        }
        float v = (lane < KK) ? (score + end_t[lane]) : -1e30f;
        float m = v;
#pragma unroll
        for (int off = 16; off > 0; off >>= 1)
            m = fmaxf(m, __shfl_xor_sync(0xffffffffu, m, off));
        float e = __expf(v - m);
#pragma unroll
        for (int off = 16; off > 0; off >>= 1)
            e += __shfl_xor_sync(0xffffffffu, e, off);
        float den = m + __logf(e);
        if (lane == 0) g_ND[b] = s_num - den;
    }
}

__global__ void finish_kernel(float* __restrict__ out, int out_n)
{
    __shared__ float s[64];
    int tid = threadIdx.x;
    s[tid] = g_ND[tid];
    __syncthreads();
    for (int st = 32; st > 0; st >>= 1) {
        if (tid < st) s[tid] += s[tid + st];
        __syncthreads();
    }
    if (tid == 0) out[0] = -s[0] / 64.f;
    if (tid > 0 && tid < out_n) out[tid] = 0.f;
}

// ---------------------------------------------------------------------------
extern "C" void kernel_launch(void* const* d_in, const int* in_sizes, int n_in,
                              void* d_out, int out_size)
{
    const float* embeds    = (const float*)d_in[0];
    const int*   tags      = (const int*)d_in[1];
    const void*  mask      = d_in[2];
    const float* w_ih_l0   = (const float*)d_in[3];
    const float* w_hh_l0   = (const float*)d_in[4];
    const float* b_ih_l0   = (const float*)d_in[5];
    const float* b_hh_l0   = (const float*)d_in[6];
    const float* w_ih_l0r  = (const float*)d_in[7];
    const float* w_hh_l0r  = (const float*)d_in[8];
    const float* b_ih_l0r  = (const float*)d_in[9];
    const float* b_hh_l0r  = (const float*)d_in[10];
    const float* w_ih_l1   = (const float*)d_in[11];
    const float* w_hh_l1   = (const float*)d_in[12];
    const float* b_ih_l1   = (const float*)d_in[13];
    const float* b_hh_l1   = (const float*)d_in[14];
    const float* w_ih_l1r  = (const float*)d_in[15];
    const float* w_hh_l1r  = (const float*)d_in[16];
    const float* b_ih_l1r  = (const float*)d_in[17];
    const float* b_hh_l1r  = (const float*)d_in[18];
    const float* linear_w  = (const float*)d_in[19];
    const float* linear_b  = (const float*)d_in[20];
    const float* start_tr  = (const float*)d_in[21];
    const float* end_tr    = (const float*)d_in[22];
    const float* trans     = (const float*)d_in[23];
    (void)in_sizes; (void)n_in;

    // ---- one-time fp16 conversions (embeds + packed w_ih weights)
    conv_f2h<<<(BB * TT * EE / 4 + 255) / 256, 256>>>(embeds, BB * TT * EE, 0, 0);
    conv_f2h<<<(512 * 768 / 4 + 255) / 256, 256>>>(w_ih_l0,  512 * 768, 1, 0);
    conv_f2h<<<(512 * 768 / 4 + 255) / 256, 256>>>(w_ih_l0r, 512 * 768, 1, 512 * 768);
    conv_f2h<<<(512 * 256 / 4 + 255) / 256, 256>>>(w_ih_l1,  512 * 256, 2, 0);
    conv_f2h<<<(512 * 256 / 4 + 255) / 256, 256>>>(w_ih_l1r, 512 * 256, 2, 512 * 256);

    dim3 ggrid(8, 256);   // N/128 x M/128

    // layer 0
    gemm_tc<0><<<ggrid, 256>>>(768, b_ih_l0, b_hh_l0, b_ih_l0r, b_hh_l0r);
    lstm_kernel<<<128, 512>>>(w_hh_l0, w_hh_l0r, 0);

    // layer 1 (A = g_H0h)
    gemm_tc<1><<<ggrid, 256>>>(256, b_ih_l1, b_hh_l1, b_ih_l1r, b_hh_l1r);
    lstm_kernel<<<128, 512>>>(w_hh_l1, w_hh_l1r, 1);

    // fused emissions + CRF
    crf_kernel<<<64, 256>>>(tags, mask, start_tr, end_tr, trans, linear_w, linear_b);
    finish_kernel<<<1, 64>>>((float*)d_out, out_size);
}

// round 13
// speedup vs baseline: 1.1954x; 1.0345x over previous
#include <cuda_runtime.h>
#include <cuda_fp16.h>
#include <cuda_bf16.h>
#include <cstdint>

// Problem constants
#define BB 64
#define TT 512
#define EE 768
#define HH 128      // hidden per direction
#define KK 11

// ---------------------------------------------------------------------------
// Scratch (device globals; no dynamic allocation allowed)
// ---------------------------------------------------------------------------
__device__ __half g_XPh[(size_t)TT * BB * 1024];  // gate x-contributions (fp16)
__device__ __half g_Eh[(size_t)BB * TT * EE];     // embeds (fp16)
__device__ __half g_W0h[1024 * 768];              // [fwd;rev] w_ih layer0 (fp16)
__device__ __half g_W1h[1024 * 256];              // [fwd;rev] w_ih layer1 (fp16)
__device__ __half g_H0h[(size_t)TT * BB * 256];   // layer0 h (fp16, gemm1 A)
__device__ __half g_H1h[(size_t)TT * BB * 256];   // layer1 h (fp16, crf input)
__device__ float  g_ND[BB];                       // num - den per batch

__device__ __forceinline__ float tanha(float x) {
    float r; asm("tanh.approx.f32 %0, %1;" : "=f"(r) : "f"(x)); return r;
}
__device__ __forceinline__ float sigt(float x) {   // sigmoid via tanh
    return fmaf(0.5f, tanha(0.5f * x), 0.5f);
}
__device__ __forceinline__ __half2 u2h2(unsigned int u) {
    __half2 r; *reinterpret_cast<unsigned int*>(&r) = u; return r;
}
__device__ __forceinline__ unsigned h2u(__half2 h) {
    return *reinterpret_cast<unsigned*>(&h);
}
__device__ __forceinline__ void mma_f16(float* d, const unsigned* a, const unsigned* b) {
    asm volatile(
        "mma.sync.aligned.m16n8k16.row.col.f32.f16.f16.f32 "
        "{%0,%1,%2,%3},{%4,%5,%6,%7},{%8,%9},{%0,%1,%2,%3};"
        : "+f"(d[0]), "+f"(d[1]), "+f"(d[2]), "+f"(d[3])
        : "r"(a[0]), "r"(a[1]), "r"(a[2]), "r"(a[3]), "r"(b[0]), "r"(b[1]));
}
__device__ __forceinline__ unsigned smem_u32(const void* p) {
    unsigned a;
    asm("{ .reg .u64 t; cvta.to.shared.u64 t, %1; cvt.u32.u64 %0, t; }"
        : "=r"(a) : "l"(p));
    return a;
}
__device__ __forceinline__ void ldsm_x4(unsigned& r0, unsigned& r1,
                                        unsigned& r2, unsigned& r3, unsigned addr) {
    asm volatile("ldmatrix.sync.aligned.m8n8.x4.shared.b16 {%0,%1,%2,%3}, [%4];"
                 : "=r"(r0), "=r"(r1), "=r"(r2), "=r"(r3) : "r"(addr));
}

// ---------------------------------------------------------------------------
// Merged fp32 -> fp16 conversion for all 5 tensors (one launch).
// Regions (in float4 units): embeds->g_Eh, w_ih_l0/(r)->g_W0h, w_ih_l1/(r)->g_W1h
// ---------------------------------------------------------------------------
#define N_EMB (BB * TT * EE)     // 25165824
#define N_W0  (512 * 768)        // 393216
#define N_W1  (512 * 256)        // 131072
#define CONV_TOTAL4 ((N_EMB + 2 * N_W0 + 2 * N_W1) / 4)

__global__ __launch_bounds__(256) void conv_all(
    const float* __restrict__ emb,
    const float* __restrict__ w0f, const float* __restrict__ w0r,
    const float* __restrict__ w1f, const float* __restrict__ w1r)
{
    long i4 = (long)blockIdx.x * 256 + threadIdx.x;
    if (i4 >= CONV_TOTAL4) return;
    long i = i4 * 4;

    const float* src;
    __half* dst;
    long off;
    if (i < N_EMB)                       { src = emb; dst = g_Eh;  off = i; }
    else if (i < N_EMB + N_W0)           { src = w0f; dst = g_W0h; off = i - N_EMB; }
    else if (i < N_EMB + 2 * N_W0)       { src = w0r; dst = g_W0h + N_W0; off = i - N_EMB - N_W0; }
    else if (i < N_EMB + 2 * N_W0 + N_W1){ src = w1f; dst = g_W1h; off = i - N_EMB - 2 * N_W0; }
    else                                 { src = w1r; dst = g_W1h + N_W1; off = i - N_EMB - 2 * N_W0 - N_W1; }

    float4 f = *reinterpret_cast<const float4*>(src + off);
    uint2 v;
    v.x = h2u(__floats2half2_rn(f.x, f.y));
    v.y = h2u(__floats2half2_rn(f.z, f.w));
    *reinterpret_cast<uint2*>(dst + off) = v;
}

// ---------------------------------------------------------------------------
// fp16 tensor-core GEMM (fp32 accum), ldmatrix + BK=32 double buffer.
//   XPh[r][n] = A[r][:].W[n][:] + bias[n]
//   AMODE 0: A=g_Eh (embeds layout: row r -> ((r&63)*512+(r>>6))*768), W=g_W0h
//   AMODE 1: A=g_H0h (row-major 256), W=g_W1h
// Tile BM=128, BN=128, BK=32 (two 16-k slabs); 8 warps (2m x 4n), warp 64x32.
// Slab SMEM: row-major [row][16 halves] (32B rows), chunk swizzle c^=((row>>2)&1).
// One __syncthreads per 32-k. Per warp per 16-k: 6 LDSM.x4 + 16 HMMA.
// ---------------------------------------------------------------------------
#define GBK 32
#define SLAB (128 * 16)              // halves per slab
#define SLABB (SLAB * 2)             // bytes per slab

template<int AMODE>
__global__ __launch_bounds__(256) void gemm_tc(
    int Kdim,
    const float* __restrict__ biF, const float* __restrict__ bhF,
    const float* __restrict__ biR, const float* __restrict__ bhR)
{
    __shared__ __half As[2][2][SLAB];   // [buf][slab]
    __shared__ __half Bs[2][2][SLAB];
    __shared__ float bias[128];

    const int tid  = threadIdx.x;
    const int lane = tid & 31, wid = tid >> 5;
    const int wm = wid >> 2, wn = wid & 3;        // 2 x 4 warp grid
    const int g = lane >> 2, tig = lane & 3;
    const int row0 = blockIdx.y * 128;
    const int col0 = blockIdx.x * 128;

    if (tid < 128) {
        int n = col0 + tid;
        bias[tid] = (n < 512) ? (biF[n] + bhF[n]) : (biR[n - 512] + bhR[n - 512]);
    }

    // ---- global load mapping: thread covers row r=(tid>>1), k-halves ak + {0,16}
    const int arow = tid >> 1;             // 0..127
    const int ak   = (tid & 1) * 8;        // 0 or 8 within each slab
    size_t aoff;
    {
        int r = row0 + arow;
        aoff = (AMODE == 0) ? ((size_t)(r & 63) * 512 + (size_t)(r >> 6)) * 768
                            : (size_t)r * 256;
    }
    const __half* Ah = (AMODE == 0) ? g_Eh : g_H0h;
    const __half* Wb = (AMODE == 0) ? g_W0h : g_W1h;
    const __half* wrow = Wb + (size_t)(col0 + arow) * Kdim;

    // ---- swizzled STS index (halves within slab)
    const int schunk = (ak >> 3) ^ ((arow >> 2) & 1);
    const int sIdx = arow * 16 + schunk * 8;

    // ---- ldmatrix per-thread byte offsets within a slab
    unsigned offA[4];
#pragma unroll
    for (int mt = 0; mt < 4; ++mt) {
        int row = wm * 64 + mt * 16 + (lane & 7) + ((lane >> 3) & 1) * 8;
        int ch  = ((lane >> 4) & 1) ^ ((row >> 2) & 1);
        offA[mt] = (unsigned)(row * 32 + ch * 16);
    }
    unsigned offB[2];
#pragma unroll
    for (int p = 0; p < 2; ++p) {
        int row = wn * 32 + p * 16 + ((lane >> 4) & 1) * 8 + (lane & 7);
        int ch  = ((lane >> 3) & 1) ^ ((row >> 2) & 1);
        offB[p] = (unsigned)(row * 32 + ch * 16);
    }
    const unsigned baseA[2] = { smem_u32(As[0][0]), smem_u32(As[1][0]) };
    const unsigned baseB[2] = { smem_u32(Bs[0][0]), smem_u32(Bs[1][0]) };

    float c[4][4][4];
#pragma unroll
    for (int i = 0; i < 4; i++)
#pragma unroll
        for (int j = 0; j < 4; j++)
#pragma unroll
            for (int q = 0; q < 4; q++) c[i][j][q] = 0.f;

    const int niter = Kdim / GBK;
    uint4 au0, au1, bu0, bu1;

    // ---- prologue: chunk 0 -> buf 0
    au0 = *reinterpret_cast<const uint4*>(Ah + aoff + ak);
    au1 = *reinterpret_cast<const uint4*>(Ah + aoff + 16 + ak);
    bu0 = *reinterpret_cast<const uint4*>(wrow + ak);
    bu1 = *reinterpret_cast<const uint4*>(wrow + 16 + ak);
    *reinterpret_cast<uint4*>(&As[0][0][sIdx]) = au0;
    *reinterpret_cast<uint4*>(&As[0][1][sIdx]) = au1;
    *reinterpret_cast<uint4*>(&Bs[0][0][sIdx]) = bu0;
    *reinterpret_cast<uint4*>(&Bs[0][1][sIdx]) = bu1;
    __syncthreads();

#pragma unroll 1
    for (int i = 0; i < niter; ++i) {
        const int pb = i & 1;
        if (i + 1 < niter) {
            const int k0 = (i + 1) * GBK;
            au0 = *reinterpret_cast<const uint4*>(Ah + aoff + k0 + ak);
            au1 = *reinterpret_cast<const uint4*>(Ah + aoff + k0 + 16 + ak);
            bu0 = *reinterpret_cast<const uint4*>(wrow + k0 + ak);
            bu1 = *reinterpret_cast<const uint4*>(wrow + k0 + 16 + ak);
        }

        // two 16-k slabs from buf pb
#pragma unroll
        for (int s = 0; s < 2; ++s) {
            const unsigned bA = baseA[pb] + s * SLABB;
            const unsigned bB = baseB[pb] + s * SLABB;
            unsigned af[4][4], bf[4][2];
#pragma unroll
            for (int mt = 0; mt < 4; ++mt)
                ldsm_x4(af[mt][0], af[mt][1], af[mt][2], af[mt][3], bA + offA[mt]);
#pragma unroll
            for (int p = 0; p < 2; ++p)
                ldsm_x4(bf[2 * p][0], bf[2 * p][1], bf[2 * p + 1][0], bf[2 * p + 1][1],
                        bB + offB[p]);
#pragma unroll
            for (int mt = 0; mt < 4; ++mt)
#pragma unroll
                for (int nt = 0; nt < 4; ++nt)
                    mma_f16(c[mt][nt], af[mt], bf[nt]);
        }

        if (i + 1 < niter) {
            const int nb = pb ^ 1;
            *reinterpret_cast<uint4*>(&As[nb][0][sIdx]) = au0;
            *reinterpret_cast<uint4*>(&As[nb][1][sIdx]) = au1;
            *reinterpret_cast<uint4*>(&Bs[nb][0][sIdx]) = bu0;
            *reinterpret_cast<uint4*>(&Bs[nb][1][sIdx]) = bu1;
        }
        __syncthreads();
    }

    // epilogue: XPh(row,col) = c + bias, packed half2
#pragma unroll
    for (int mt = 0; mt < 4; ++mt) {
#pragma unroll
        for (int nt = 0; nt < 4; ++nt) {
            int r  = row0 + wm * 64 + mt * 16 + g;
            int cb = wn * 32 + nt * 8 + 2 * tig;
            int col = col0 + cb;
            unsigned p0 = h2u(__floats2half2_rn(c[mt][nt][0] + bias[cb],
                                                c[mt][nt][1] + bias[cb + 1]));
            unsigned p1 = h2u(__floats2half2_rn(c[mt][nt][2] + bias[cb],
                                                c[mt][nt][3] + bias[cb + 1]));
            *reinterpret_cast<unsigned*>(&g_XPh[(size_t)r * 1024 + col]) = p0;
            *reinterpret_cast<unsigned*>(&g_XPh[(size_t)(r + 8) * 1024 + col]) = p1;
        }
    }
}

// ---------------------------------------------------------------------------
// LSTM recurrence: one block per (batch, dir). 512 threads = 16 warps.
// (unchanged R12 config — measured best)
// ---------------------------------------------------------------------------
__global__ __launch_bounds__(512) void lstm_kernel(
    const float* __restrict__ whh_fwd, const float* __restrict__ whh_rev, int layer)
{
    __shared__ uint4 hbuf4[2][16];   // 2 x 128 halves

    const int b   = blockIdx.x >> 1;
    const int dir = blockIdx.x & 1;
    const float* whh = dir ? whh_rev : whh_fwd;

    const int lane = threadIdx.x & 31;
    const int wid  = threadIdx.x >> 5;
    const int u    = wid * 8 + (lane & 7);
    const int gate = lane >> 3;
    const int wrow_idx = gate * 128 + u;

    // weights -> registers (fp16)
    __half2 W[64];
    {
        const float4* wr4 = reinterpret_cast<const float4*>(whh + (size_t)wrow_idx * 128);
#pragma unroll
        for (int i = 0; i < 32; ++i) {
            float4 f = wr4[i];
            W[2 * i]     = __floats2half2_rn(f.x, f.y);
            W[2 * i + 1] = __floats2half2_rn(f.z, f.w);
        }
    }
    if (threadIdx.x < 16) hbuf4[0][threadIdx.x] = make_uint4(0u, 0u, 0u, 0u);
    float cst = 0.f;
    __syncthreads();

    const long xstride = dir ? -(long)(BB * 1024) : (long)(BB * 1024);
    const long hstride = dir ? -(long)(BB * 256)  : (long)(BB * 256);
    const size_t hbase = (size_t)(dir ? (TT - 1) : 0) * (BB * 256)
                       + (size_t)b * 256 + dir * 128 + u;
    const __half* xp_p = g_XPh + (size_t)(dir ? (TT - 1) : 0) * (BB * 1024)
                               + (size_t)b * 1024 + dir * 512 + wrow_idx;
    __half* hout_p = (layer ? g_H1h : g_H0h) + hbase;

    __half xp = *xp_p;

#pragma unroll 2
    for (int t = 0; t < TT; ++t) {
        const __half* pf = xp_p + ((t < TT - 1) ? xstride : 0);
        __half xpn = *pf;

        const uint4* hb = hbuf4[t & 1];
        __half2 s0 = __floats2half2_rn(0.f, 0.f);
        __half2 s1 = s0, s2 = s0, s3 = s0;
#pragma unroll
        for (int k = 0; k < 4; ++k) {
            uint4 ha = hb[4 * k];
            uint4 hc = hb[4 * k + 1];
            uint4 hd = hb[4 * k + 2];
            uint4 he = hb[4 * k + 3];
            s0 = __hfma2(W[16 * k + 0],  u2h2(ha.x), s0);
            s1 = __hfma2(W[16 * k + 1],  u2h2(ha.y), s1);
            s2 = __hfma2(W[16 * k + 2],  u2h2(ha.z), s2);
            s3 = __hfma2(W[16 * k + 3],  u2h2(ha.w), s3);
            s0 = __hfma2(W[16 * k + 4],  u2h2(hc.x), s0);
            s1 = __hfma2(W[16 * k + 5],  u2h2(hc.y), s1);
            s2 = __hfma2(W[16 * k + 6],  u2h2(hc.z), s2);
            s3 = __hfma2(W[16 * k + 7],  u2h2(hc.w), s3);
            s0 = __hfma2(W[16 * k + 8],  u2h2(hd.x), s0);
            s1 = __hfma2(W[16 * k + 9],  u2h2(hd.y), s1);
            s2 = __hfma2(W[16 * k + 10], u2h2(hd.z), s2);
            s3 = __hfma2(W[16 * k + 11], u2h2(hd.w), s3);
            s0 = __hfma2(W[16 * k + 12], u2h2(he.x), s0);
            s1 = __hfma2(W[16 * k + 13], u2h2(he.y), s1);
            s2 = __hfma2(W[16 * k + 14], u2h2(he.z), s2);
            s3 = __hfma2(W[16 * k + 15], u2h2(he.w), s3);
        }
        __half2 sh = __hadd2(__hadd2(s0, s1), __hadd2(s2, s3));
        __half  gh = __hadd(__hadd(__low2half(sh), __high2half(sh)), xp);
        const float gval = __half2float(gh);

        const float act = (gate == 2) ? tanha(gval) : sigt(gval);

        const int src = lane & 7;
        float iv = __shfl_sync(0xffffffffu, act, src);
        float fv = __shfl_sync(0xffffffffu, act, src + 8);
        float gv = __shfl_sync(0xffffffffu, act, src + 16);
        float ov = __shfl_sync(0xffffffffu, act, src + 24);

        if (lane < 8) {
            float cn = fv * cst + iv * gv;
            cst = cn;
            float hn = ov * tanha(cn);
            __half hcvt = __float2half_rn(hn);
            reinterpret_cast<__half*>(&hbuf4[(t & 1) ^ 1][0])[u] = hcvt;
            *hout_p = hcvt;
        }
        xp = xpn;
        xp_p += xstride;
        hout_p += hstride;
        __syncthreads();
    }
}

// ---------------------------------------------------------------------------
// CRF (fused emissions): one block per batch.  (unchanged R12)
// ---------------------------------------------------------------------------
__global__ __launch_bounds__(256) void crf_kernel(
    const int* __restrict__ tags, const void* __restrict__ maskraw,
    const float* __restrict__ start_t, const float* __restrict__ end_t,
    const float* __restrict__ trans,
    const float* __restrict__ lw, const float* __restrict__ lb)
{
    __shared__ float ems[TT * 12];
    __shared__ float redf[256];
    __shared__ int   redi[256];
    __shared__ unsigned char maskb[TT];
    __shared__ float s_num;

    const int b = blockIdx.x;
    const int tid = threadIdx.x;

    {
        const unsigned char* mc = reinterpret_cast<const unsigned char*>(maskraw);
        const bool bytewise = (mc[1] != 0);
        const int* mi = reinterpret_cast<const int*>(maskraw);
        for (int t = tid; t < TT; t += 256) {
            maskb[t] = bytewise ? (mc[(size_t)b * TT + t] != 0)
                                : (mi[(size_t)b * TT + t] != 0);
        }
    }

    // ---- fused emissions
    for (int base = tid; base < TT * 16; base += 256) {
        int t = base >> 4, n = base & 15;
        if (n < KK) {
            const uint4*  h4 = reinterpret_cast<const uint4*>(
                &g_H1h[((size_t)t * BB + b) * 256]);
            const float4* w4 = reinterpret_cast<const float4*>(lw + (size_t)n * 256);
            float acc = 0.f;
#pragma unroll 8
            for (int k = 0; k < 32; ++k) {
                uint4 hv = h4[k];
                float4 w0 = w4[2 * k], w1 = w4[2 * k + 1];
                float2 a0 = __half22float2(u2h2(hv.x));
                float2 a1 = __half22float2(u2h2(hv.y));
                float2 a2 = __half22float2(u2h2(hv.z));
                float2 a3 = __half22float2(u2h2(hv.w));
                acc += a0.x * w0.x + a0.y * w0.y + a1.x * w0.z + a1.y * w0.w;
                acc += a2.x * w1.x + a2.y * w1.y + a3.x * w1.z + a3.y * w1.w;
            }
            ems[t * 12 + n] = acc + lb[n];
        }
    }
    __syncthreads();

    // ---- numerator (parallel over t)
    float part = 0.f;
    int   cnt  = 0;
    for (int t = tid; t < TT; t += 256) cnt += maskb[t] ? 1 : 0;
    for (int t = 1 + tid; t < TT; t += 256) {
        if (maskb[t]) {
            int tp = tags[(size_t)b * TT + t - 1];
            int tc = tags[(size_t)b * TT + t];
            part += trans[tp * KK + tc] + ems[t * 12 + tc];
        }
    }
    redf[tid] = part; redi[tid] = cnt;
    __syncthreads();
    for (int s = 128; s > 0; s >>= 1) {
        if (tid < s) { redf[tid] += redf[tid + s]; redi[tid] += redi[tid + s]; }
        __syncthreads();
    }
    if (tid == 0) {
        int t0 = tags[(size_t)b * TT];
        int seqEnd = redi[0] - 1;
        s_num = start_t[t0] + ems[t0] + redf[0]
              + end_t[tags[(size_t)b * TT + seqEnd]];
    }
    __syncthreads();

    // ---- denominator (warp 0, baseline-rescaled forward algorithm)
    if (tid < 32) {
        const int lane = tid;
        float etcol[KK];
        if (lane < KK) {
#pragma unroll
            for (int i = 0; i < KK; i++) etcol[i] = __expf(trans[i * KK + lane]);
        } else {
#pragma unroll
            for (int i = 0; i < KK; i++) etcol[i] = 0.f;
        }
        float score = (lane < KK) ? (start_t[lane] + ems[lane]) : -1e30f;

        for (int t = 1; t < TT; ++t) {
            if (maskb[t]) {
                float m = __shfl_sync(0xffffffffu, score, 0);
                float e = __expf(score - m);
                float dot = 0.f;
#pragma unroll
                for (int i = 0; i < KK; i++)
                    dot = fmaf(__shfl_sync(0xffffffffu, e, i), etcol[i], dot);
                float nxt = m + __logf(dot) + ems[t * 12 + lane];
                if (lane < KK) score = nxt;
            }
        }
        float v = (lane < KK) ? (score + end_t[lane]) : -1e30f;
        float m = v;
#pragma unroll
        for (int off = 16; off > 0; off >>= 1)
            m = fmaxf(m, __shfl_xor_sync(0xffffffffu, m, off));
        float e = __expf(v - m);
#pragma unroll
        for (int off = 16; off > 0; off >>= 1)
            e += __shfl_xor_sync(0xffffffffu, e, off);
        float den = m + __logf(e);
        if (lane == 0) g_ND[b] = s_num - den;
    }
}

__global__ void finish_kernel(float* __restrict__ out, int out_n)
{
    __shared__ float s[64];
    int tid = threadIdx.x;
    s[tid] = g_ND[tid];
    __syncthreads();
    for (int st = 32; st > 0; st >>= 1) {
        if (tid < st) s[tid] += s[tid + st];
        __syncthreads();
    }
    if (tid == 0) out[0] = -s[0] / 64.f;
    if (tid > 0 && tid < out_n) out[tid] = 0.f;
}

// ---------------------------------------------------------------------------
extern "C" void kernel_launch(void* const* d_in, const int* in_sizes, int n_in,
                              void* d_out, int out_size)
{
    const float* embeds    = (const float*)d_in[0];
    const int*   tags      = (const int*)d_in[1];
    const void*  mask      = d_in[2];
    const float* w_ih_l0   = (const float*)d_in[3];
    const float* w_hh_l0   = (const float*)d_in[4];
    const float* b_ih_l0   = (const float*)d_in[5];
    const float* b_hh_l0   = (const float*)d_in[6];
    const float* w_ih_l0r  = (const float*)d_in[7];
    const float* w_hh_l0r  = (const float*)d_in[8];
    const float* b_ih_l0r  = (const float*)d_in[9];
    const float* b_hh_l0r  = (const float*)d_in[10];
    const float* w_ih_l1   = (const float*)d_in[11];
    const float* w_hh_l1   = (const float*)d_in[12];
    const float* b_ih_l1   = (const float*)d_in[13];
    const float* b_hh_l1   = (const float*)d_in[14];
    const float* w_ih_l1r  = (const float*)d_in[15];
    const float* w_hh_l1r  = (const float*)d_in[16];
    const float* b_ih_l1r  = (const float*)d_in[17];
    const float* b_hh_l1r  = (const float*)d_in[18];
    const float* linear_w  = (const float*)d_in[19];
    const float* linear_b  = (const float*)d_in[20];
    const float* start_tr  = (const float*)d_in[21];
    const float* end_tr    = (const float*)d_in[22];
    const float* trans     = (const float*)d_in[23];
    (void)in_sizes; (void)n_in;

    // ---- one merged fp16 conversion launch
    conv_all<<<(CONV_TOTAL4 + 255) / 256, 256>>>(embeds, w_ih_l0, w_ih_l0r,
                                                 w_ih_l1, w_ih_l1r);

    dim3 ggrid(8, 256);   // N/128 x M/128

    // layer 0
    gemm_tc<0><<<ggrid, 256>>>(768, b_ih_l0, b_hh_l0, b_ih_l0r, b_hh_l0r);
    lstm_kernel<<<128, 512>>>(w_hh_l0, w_hh_l0r, 0);

    // layer 1 (A = g_H0h)
    gemm_tc<1><<<ggrid, 256>>>(256, b_ih_l1, b_hh_l1, b_ih_l1r, b_hh_l1r);
    lstm_kernel<<<128, 512>>>(w_hh_l1, w_hh_l1r, 1);

    // fused emissions + CRF
    crf_kernel<<<64, 256>>>(tags, mask, start_tr, end_tr, trans, linear_w, linear_b);
    finish_kernel<<<1, 64>>>((float*)d_out, out_size);
}

// round 14
// speedup vs baseline: 1.1992x; 1.0031x over previous
#include <cuda_runtime.h>
#include <cuda_fp16.h>
#include <cuda_bf16.h>
#include <cstdint>

// Problem constants
#define BB 64
#define TT 512
#define EE 768
#define HH 128      // hidden per direction
#define KK 11

// ---------------------------------------------------------------------------
// Scratch (device globals; no dynamic allocation allowed)
// ---------------------------------------------------------------------------
__device__ __half g_XPh[(size_t)TT * BB * 1024];  // gate x-contributions (fp16)
__device__ __half g_Eh[(size_t)BB * TT * EE];     // embeds (fp16, r-major: r=t*64+b)
__device__ __half g_W0h[1024 * 768];              // [fwd;rev] w_ih layer0 (fp16)
__device__ __half g_W1h[1024 * 256];              // [fwd;rev] w_ih layer1 (fp16)
__device__ __half g_H0h[(size_t)TT * BB * 256];   // layer0 h (fp16, gemm1 A)
__device__ __half g_H1h[(size_t)TT * BB * 256];   // layer1 h (fp16, crf input)
__device__ float  g_ND[BB];                       // num - den per batch

__device__ __forceinline__ float tanha(float x) {
    float r; asm("tanh.approx.f32 %0, %1;" : "=f"(r) : "f"(x)); return r;
}
__device__ __forceinline__ float sigt(float x) {   // sigmoid via tanh
    return fmaf(0.5f, tanha(0.5f * x), 0.5f);
}
__device__ __forceinline__ __half2 u2h2(unsigned int u) {
    __half2 r; *reinterpret_cast<unsigned int*>(&r) = u; return r;
}
__device__ __forceinline__ unsigned h2u(__half2 h) {
    return *reinterpret_cast<unsigned*>(&h);
}
__device__ __forceinline__ void mma_f16(float* d, const unsigned* a, const unsigned* b) {
    asm volatile(
        "mma.sync.aligned.m16n8k16.row.col.f32.f16.f16.f32 "
        "{%0,%1,%2,%3},{%4,%5,%6,%7},{%8,%9},{%0,%1,%2,%3};"
        : "+f"(d[0]), "+f"(d[1]), "+f"(d[2]), "+f"(d[3])
        : "r"(a[0]), "r"(a[1]), "r"(a[2]), "r"(a[3]), "r"(b[0]), "r"(b[1]));
}
__device__ __forceinline__ unsigned smem_u32(const void* p) {
    unsigned a;
    asm("{ .reg .u64 t; cvta.to.shared.u64 t, %1; cvt.u32.u64 %0, t; }"
        : "=r"(a) : "l"(p));
    return a;
}
__device__ __forceinline__ void ldsm_x4(unsigned& r0, unsigned& r1,
                                        unsigned& r2, unsigned& r3, unsigned addr) {
    asm volatile("ldmatrix.sync.aligned.m8n8.x4.shared.b16 {%0,%1,%2,%3}, [%4];"
                 : "=r"(r0), "=r"(r1), "=r"(r2), "=r"(r3) : "r"(addr));
}

// ---------------------------------------------------------------------------
// Merged fp32 -> fp16 conversion (one launch).
// embeds: row-permuted into r-major (r = t*64+b); rows are 768 contiguous
// floats, so both read and write are fully coalesced (192 thr / row).
// weights: straight copy-convert.
// ---------------------------------------------------------------------------
#define N_EMB (BB * TT * EE)     // 25165824
#define N_W0  (512 * 768)        // 393216
#define N_W1  (512 * 256)        // 131072
#define CONV_TOTAL4 ((N_EMB + 2 * N_W0 + 2 * N_W1) / 4)
#define E4 (EE / 4)              // 192 float4 per row

__global__ __launch_bounds__(256) void conv_all(
    const float* __restrict__ emb,
    const float* __restrict__ w0f, const float* __restrict__ w0r,
    const float* __restrict__ w1f, const float* __restrict__ w1r)
{
    long i4 = (long)blockIdx.x * 256 + threadIdx.x;
    if (i4 >= CONV_TOTAL4) return;
    long i = i4 * 4;

    const float* src;
    __half* dst;
    long soff, doff;
    if (i < N_EMB) {
        // output element index i -> row r = i/768, e = i%768
        long r = i4 / E4;
        long e4 = i4 - r * E4;
        long b = r & 63, t = r >> 6;
        soff = (b * TT + t) * EE + e4 * 4;   // input row (b,t), contiguous
        doff = i;                             // output r-major, contiguous
        src = emb; dst = g_Eh;
    } else if (i < N_EMB + N_W0)            { src = w0f; dst = g_W0h; soff = doff = i - N_EMB; }
    else if (i < N_EMB + 2 * N_W0)          { src = w0r; dst = g_W0h + N_W0; soff = doff = i - N_EMB - N_W0; }
    else if (i < N_EMB + 2 * N_W0 + N_W1)   { src = w1f; dst = g_W1h; soff = doff = i - N_EMB - 2 * N_W0; }
    else                                    { src = w1r; dst = g_W1h + N_W1; soff = doff = i - N_EMB - 2 * N_W0 - N_W1; }

    float4 f = *reinterpret_cast<const float4*>(src + soff);
    uint2 v;
    v.x = h2u(__floats2half2_rn(f.x, f.y));
    v.y = h2u(__floats2half2_rn(f.z, f.w));
    *reinterpret_cast<uint2*>(dst + doff) = v;
}

// ---------------------------------------------------------------------------
// fp16 tensor-core GEMM (fp32 accum), ldmatrix + BK=32 double buffer.
//   XPh[r][n] = A[r][:].W[n][:] + bias[n]
//   AMODE 0: A=g_Eh (r-major 768), W=g_W0h
//   AMODE 1: A=g_H0h (r-major 256), W=g_W1h
// Tile BM=128, BN=128, BK=32 (two 16-k slabs); 8 warps (2m x 4n), warp 64x32.
// Slab SMEM: row-major [row][16 halves] (32B rows), chunk swizzle c^=((row>>2)&1).
// ---------------------------------------------------------------------------
#define GBK 32
#define SLAB (128 * 16)              // halves per slab
#define SLABB (SLAB * 2)             // bytes per slab

template<int AMODE>
__global__ __launch_bounds__(256, 2) void gemm_tc(
    int Kdim,
    const float* __restrict__ biF, const float* __restrict__ bhF,
    const float* __restrict__ biR, const float* __restrict__ bhR)
{
    __shared__ __half As[2][2][SLAB];   // [buf][slab]
    __shared__ __half Bs[2][2][SLAB];
    __shared__ float bias[128];

    const int tid  = threadIdx.x;
    const int lane = tid & 31, wid = tid >> 5;
    const int wm = wid >> 2, wn = wid & 3;        // 2 x 4 warp grid
    const int g = lane >> 2, tig = lane & 3;
    const int row0 = blockIdx.y * 128;
    const int col0 = blockIdx.x * 128;

    if (tid < 128) {
        int n = col0 + tid;
        bias[tid] = (n < 512) ? (biF[n] + bhF[n]) : (biR[n - 512] + bhR[n - 512]);
    }

    // ---- global load mapping: thread covers row r=(tid>>1), k-halves ak + {0,16}
    const int arow = tid >> 1;             // 0..127
    const int ak   = (tid & 1) * 8;        // 0 or 8 within each slab
    const size_t aoff = (size_t)(row0 + arow) * (size_t)Kdim;   // linear A rows
    const __half* Ah = (AMODE == 0) ? g_Eh : g_H0h;
    const __half* Wb = (AMODE == 0) ? g_W0h : g_W1h;
    const __half* wrow = Wb + (size_t)(col0 + arow) * Kdim;

    // ---- swizzled STS index (halves within slab)
    const int schunk = (ak >> 3) ^ ((arow >> 2) & 1);
    const int sIdx = arow * 16 + schunk * 8;

    // ---- ldmatrix per-thread byte offsets within a slab
    unsigned offA[4];
#pragma unroll
    for (int mt = 0; mt < 4; ++mt) {
        int row = wm * 64 + mt * 16 + (lane & 7) + ((lane >> 3) & 1) * 8;
        int ch  = ((lane >> 4) & 1) ^ ((row >> 2) & 1);
        offA[mt] = (unsigned)(row * 32 + ch * 16);
    }
    unsigned offB[2];
#pragma unroll
    for (int p = 0; p < 2; ++p) {
        int row = wn * 32 + p * 16 + ((lane >> 4) & 1) * 8 + (lane & 7);
        int ch  = ((lane >> 3) & 1) ^ ((row >> 2) & 1);
        offB[p] = (unsigned)(row * 32 + ch * 16);
    }
    const unsigned baseA[2] = { smem_u32(As[0][0]), smem_u32(As[1][0]) };
    const unsigned baseB[2] = { smem_u32(Bs[0][0]), smem_u32(Bs[1][0]) };

    float c[4][4][4];
#pragma unroll
    for (int i = 0; i < 4; i++)
#pragma unroll
        for (int j = 0; j < 4; j++)
#pragma unroll
            for (int q = 0; q < 4; q++) c[i][j][q] = 0.f;

    const int niter = Kdim / GBK;
    uint4 au0, au1, bu0, bu1;

    // ---- prologue: chunk 0 -> buf 0
    au0 = *reinterpret_cast<const uint4*>(Ah + aoff + ak);
    au1 = *reinterpret_cast<const uint4*>(Ah + aoff + 16 + ak);
    bu0 = *reinterpret_cast<const uint4*>(wrow + ak);
    bu1 = *reinterpret_cast<const uint4*>(wrow + 16 + ak);
    *reinterpret_cast<uint4*>(&As[0][0][sIdx]) = au0;
    *reinterpret_cast<uint4*>(&As[0][1][sIdx]) = au1;
    *reinterpret_cast<uint4*>(&Bs[0][0][sIdx]) = bu0;
    *reinterpret_cast<uint4*>(&Bs[0][1][sIdx]) = bu1;
    __syncthreads();

#pragma unroll 1
    for (int i = 0; i < niter; ++i) {
        const int pb = i & 1;
        if (i + 1 < niter) {
            const int k0 = (i + 1) * GBK;
            au0 = *reinterpret_cast<const uint4*>(Ah + aoff + k0 + ak);
            au1 = *reinterpret_cast<const uint4*>(Ah + aoff + k0 + 16 + ak);
            bu0 = *reinterpret_cast<const uint4*>(wrow + k0 + ak);
            bu1 = *reinterpret_cast<const uint4*>(wrow + k0 + 16 + ak);
        }

        // two 16-k slabs from buf pb
#pragma unroll
        for (int s = 0; s < 2; ++s) {
            const unsigned bA = baseA[pb] + s * SLABB;
            const unsigned bB = baseB[pb] + s * SLABB;
            unsigned af[4][4], bf[4][2];
#pragma unroll
            for (int mt = 0; mt < 4; ++mt)
                ldsm_x4(af[mt][0], af[mt][1], af[mt][2], af[mt][3], bA + offA[mt]);
#pragma unroll
            for (int p = 0; p < 2; ++p)
                ldsm_x4(bf[2 * p][0], bf[2 * p][1], bf[2 * p + 1][0], bf[2 * p + 1][1],
                        bB + offB[p]);
#pragma unroll
            for (int mt = 0; mt < 4; ++mt)
#pragma unroll
                for (int nt = 0; nt < 4; ++nt)
                    mma_f16(c[mt][nt], af[mt], bf[nt]);
        }

        if (i + 1 < niter) {
            const int nb = pb ^ 1;
            *reinterpret_cast<uint4*>(&As[nb][0][sIdx]) = au0;
            *reinterpret_cast<uint4*>(&As[nb][1][sIdx]) = au1;
            *reinterpret_cast<uint4*>(&Bs[nb][0][sIdx]) = bu0;
            *reinterpret_cast<uint4*>(&Bs[nb][1][sIdx]) = bu1;
        }
        __syncthreads();
    }

    // epilogue: XPh(row,col) = c + bias, packed half2
#pragma unroll
    for (int mt = 0; mt < 4; ++mt) {
#pragma unroll
        for (int nt = 0; nt < 4; ++nt) {
            int r  = row0 + wm * 64 + mt * 16 + g;
            int cb = wn * 32 + nt * 8 + 2 * tig;
            int col = col0 + cb;
            unsigned p0 = h2u(__floats2half2_rn(c[mt][nt][0] + bias[cb],
                                                c[mt][nt][1] + bias[cb + 1]));
            unsigned p1 = h2u(__floats2half2_rn(c[mt][nt][2] + bias[cb],
                                                c[mt][nt][3] + bias[cb + 1]));
            *reinterpret_cast<unsigned*>(&g_XPh[(size_t)r * 1024 + col]) = p0;
            *reinterpret_cast<unsigned*>(&g_XPh[(size_t)(r + 8) * 1024 + col]) = p1;
        }
    }
}

// ---------------------------------------------------------------------------
// LSTM recurrence: one block per (batch, dir). 512 threads = 16 warps.
// (unchanged R13 config — measured best)
// ---------------------------------------------------------------------------
__global__ __launch_bounds__(512) void lstm_kernel(
    const float* __restrict__ whh_fwd, const float* __restrict__ whh_rev, int layer)
{
    __shared__ uint4 hbuf4[2][16];   // 2 x 128 halves

    const int b   = blockIdx.x >> 1;
    const int dir = blockIdx.x & 1;
    const float* whh = dir ? whh_rev : whh_fwd;

    const int lane = threadIdx.x & 31;
    const int wid  = threadIdx.x >> 5;
    const int u    = wid * 8 + (lane & 7);
    const int gate = lane >> 3;
    const int wrow_idx = gate * 128 + u;

    // weights -> registers (fp16)
    __half2 W[64];
    {
        const float4* wr4 = reinterpret_cast<const float4*>(whh + (size_t)wrow_idx * 128);
#pragma unroll
        for (int i = 0; i < 32; ++i) {
            float4 f = wr4[i];
            W[2 * i]     = __floats2half2_rn(f.x, f.y);
            W[2 * i + 1] = __floats2half2_rn(f.z, f.w);
        }
    }
    if (threadIdx.x < 16) hbuf4[0][threadIdx.x] = make_uint4(0u, 0u, 0u, 0u);
    float cst = 0.f;
    __syncthreads();

    const long xstride = dir ? -(long)(BB * 1024) : (long)(BB * 1024);
    const long hstride = dir ? -(long)(BB * 256)  : (long)(BB * 256);
    const size_t hbase = (size_t)(dir ? (TT - 1) : 0) * (BB * 256)
                       + (size_t)b * 256 + dir * 128 + u;
    const __half* xp_p = g_XPh + (size_t)(dir ? (TT - 1) : 0) * (BB * 1024)
                               + (size_t)b * 1024 + dir * 512 + wrow_idx;
    __half* hout_p = (layer ? g_H1h : g_H0h) + hbase;

    __half xp = *xp_p;

#pragma unroll 2
    for (int t = 0; t < TT; ++t) {
        const __half* pf = xp_p + ((t < TT - 1) ? xstride : 0);
        __half xpn = *pf;

        const uint4* hb = hbuf4[t & 1];
        __half2 s0 = __floats2half2_rn(0.f, 0.f);
        __half2 s1 = s0, s2 = s0, s3 = s0;
#pragma unroll
        for (int k = 0; k < 4; ++k) {
            uint4 ha = hb[4 * k];
            uint4 hc = hb[4 * k + 1];
            uint4 hd = hb[4 * k + 2];
            uint4 he = hb[4 * k + 3];
            s0 = __hfma2(W[16 * k + 0],  u2h2(ha.x), s0);
            s1 = __hfma2(W[16 * k + 1],  u2h2(ha.y), s1);
            s2 = __hfma2(W[16 * k + 2],  u2h2(ha.z), s2);
            s3 = __hfma2(W[16 * k + 3],  u2h2(ha.w), s3);
            s0 = __hfma2(W[16 * k + 4],  u2h2(hc.x), s0);
            s1 = __hfma2(W[16 * k + 5],  u2h2(hc.y), s1);
            s2 = __hfma2(W[16 * k + 6],  u2h2(hc.z), s2);
            s3 = __hfma2(W[16 * k + 7],  u2h2(hc.w), s3);
            s0 = __hfma2(W[16 * k + 8],  u2h2(hd.x), s0);
            s1 = __hfma2(W[16 * k + 9],  u2h2(hd.y), s1);
            s2 = __hfma2(W[16 * k + 10], u2h2(hd.z), s2);
            s3 = __hfma2(W[16 * k + 11], u2h2(hd.w), s3);
            s0 = __hfma2(W[16 * k + 12], u2h2(he.x), s0);
            s1 = __hfma2(W[16 * k + 13], u2h2(he.y), s1);
            s2 = __hfma2(W[16 * k + 14], u2h2(he.z), s2);
            s3 = __hfma2(W[16 * k + 15], u2h2(he.w), s3);
        }
        __half2 sh = __hadd2(__hadd2(s0, s1), __hadd2(s2, s3));
        __half  gh = __hadd(__hadd(__low2half(sh), __high2half(sh)), xp);
        const float gval = __half2float(gh);

        const float act = (gate == 2) ? tanha(gval) : sigt(gval);

        const int src = lane & 7;
        float iv = __shfl_sync(0xffffffffu, act, src);
        float fv = __shfl_sync(0xffffffffu, act, src + 8);
        float gv = __shfl_sync(0xffffffffu, act, src + 16);
        float ov = __shfl_sync(0xffffffffu, act, src + 24);

        if (lane < 8) {
            float cn = fv * cst + iv * gv;
            cst = cn;
            float hn = ov * tanha(cn);
            __half hcvt = __float2half_rn(hn);
            reinterpret_cast<__half*>(&hbuf4[(t & 1) ^ 1][0])[u] = hcvt;
            *hout_p = hcvt;
        }
        xp = xpn;
        xp_p += xstride;
        hout_p += hstride;
        __syncthreads();
    }
}

// ---------------------------------------------------------------------------
// CRF (fused emissions): one block per batch.  (unchanged R13)
// ---------------------------------------------------------------------------
__global__ __launch_bounds__(256) void crf_kernel(
    const int* __restrict__ tags, const void* __restrict__ maskraw,
    const float* __restrict__ start_t, const float* __restrict__ end_t,
    const float* __restrict__ trans,
    const float* __restrict__ lw, const float* __restrict__ lb)
{
    __shared__ float ems[TT * 12];
    __shared__ float redf[256];
    __shared__ int   redi[256];
    __shared__ unsigned char maskb[TT];
    __shared__ float s_num;

    const int b = blockIdx.x;
    const int tid = threadIdx.x;

    {
        const unsigned char* mc = reinterpret_cast<const unsigned char*>(maskraw);
        const bool bytewise = (mc[1] != 0);
        const int* mi = reinterpret_cast<const int*>(maskraw);
        for (int t = tid; t < TT; t += 256) {
            maskb[t] = bytewise ? (mc[(size_t)b * TT + t] != 0)
                                : (mi[(size_t)b * TT + t] != 0);
        }
    }

    // ---- fused emissions
    for (int base = tid; base < TT * 16; base += 256) {
        int t = base >> 4, n = base & 15;
        if (n < KK) {
            const uint4*  h4 = reinterpret_cast<const uint4*>(
                &g_H1h[((size_t)t * BB + b) * 256]);
            const float4* w4 = reinterpret_cast<const float4*>(lw + (size_t)n * 256);
            float acc = 0.f;
#pragma unroll 8
            for (int k = 0; k < 32; ++k) {
                uint4 hv = h4[k];
                float4 w0 = w4[2 * k], w1 = w4[2 * k + 1];
                float2 a0 = __half22float2(u2h2(hv.x));
                float2 a1 = __half22float2(u2h2(hv.y));
                float2 a2 = __half22float2(u2h2(hv.z));
                float2 a3 = __half22float2(u2h2(hv.w));
                acc += a0.x * w0.x + a0.y * w0.y + a1.x * w0.z + a1.y * w0.w;
                acc += a2.x * w1.x + a2.y * w1.y + a3.x * w1.z + a3.y * w1.w;
            }
            ems[t * 12 + n] = acc + lb[n];
        }
    }
    __syncthreads();

    // ---- numerator (parallel over t)
    float part = 0.f;
    int   cnt  = 0;
    for (int t = tid; t < TT; t += 256) cnt += maskb[t] ? 1 : 0;
    for (int t = 1 + tid; t < TT; t += 256) {
        if (maskb[t]) {
            int tp = tags[(size_t)b * TT + t - 1];
            int tc = tags[(size_t)b * TT + t];
            part += trans[tp * KK + tc] + ems[t * 12 + tc];
        }
    }
    redf[tid] = part; redi[tid] = cnt;
    __syncthreads();
    for (int s = 128; s > 0; s >>= 1) {
        if (tid < s) { redf[tid] += redf[tid + s]; redi[tid] += redi[tid + s]; }
        __syncthreads();
    }
    if (tid == 0) {
        int t0 = tags[(size_t)b * TT];
        int seqEnd = redi[0] - 1;
        s_num = start_t[t0] + ems[t0] + redf[0]
              + end_t[tags[(size_t)b * TT + seqEnd]];
    }
    __syncthreads();

    // ---- denominator (warp 0, baseline-rescaled forward algorithm)
    if (tid < 32) {
        const int lane = tid;
        float etcol[KK];
        if (lane < KK) {
#pragma unroll
            for (int i = 0; i < KK; i++) etcol[i] = __expf(trans[i * KK + lane]);
        } else {
#pragma unroll
            for (int i = 0; i < KK; i++) etcol[i] = 0.f;
        }
        float score = (lane < KK) ? (start_t[lane] + ems[lane]) : -1e30f;

        for (int t = 1; t < TT; ++t) {
            if (maskb[t]) {
                float m = __shfl_sync(0xffffffffu, score, 0);
                float e = __expf(score - m);
                float dot = 0.f;
#pragma unroll
                for (int i = 0; i < KK; i++)
                    dot = fmaf(__shfl_sync(0xffffffffu, e, i), etcol[i], dot);
                float nxt = m + __logf(dot) + ems[t * 12 + lane];
                if (lane < KK) score = nxt;
            }
        }
        float v = (lane < KK) ? (score + end_t[lane]) : -1e30f;
        float m = v;
#pragma unroll
        for (int off = 16; off > 0; off >>= 1)
            m = fmaxf(m, __shfl_xor_sync(0xffffffffu, m, off));
        float e = __expf(v - m);
#pragma unroll
        for (int off = 16; off > 0; off >>= 1)
            e += __shfl_xor_sync(0xffffffffu, e, off);
        float den = m + __logf(e);
        if (lane == 0) g_ND[b] = s_num - den;
    }
}

__global__ void finish_kernel(float* __restrict__ out, int out_n)
{
    __shared__ float s[64];
    int tid = threadIdx.x;
    s[tid] = g_ND[tid];
    __syncthreads();
    for (int st = 32; st > 0; st >>= 1) {
        if (tid < st) s[tid] += s[tid + st];
        __syncthreads();
    }
    if (tid == 0) out[0] = -s[0] / 64.f;
    if (tid > 0 && tid < out_n) out[tid] = 0.f;
}

// ---------------------------------------------------------------------------
extern "C" void kernel_launch(void* const* d_in, const int* in_sizes, int n_in,
                              void* d_out, int out_size)
{
    const float* embeds    = (const float*)d_in[0];
    const int*   tags      = (const int*)d_in[1];
    const void*  mask      = d_in[2];
    const float* w_ih_l0   = (const float*)d_in[3];
    const float* w_hh_l0   = (const float*)d_in[4];
    const float* b_ih_l0   = (const float*)d_in[5];
    const float* b_hh_l0   = (const float*)d_in[6];
    const float* w_ih_l0r  = (const float*)d_in[7];
    const float* w_hh_l0r  = (const float*)d_in[8];
    const float* b_ih_l0r  = (const float*)d_in[9];
    const float* b_hh_l0r  = (const float*)d_in[10];
    const float* w_ih_l1   = (const float*)d_in[11];
    const float* w_hh_l1   = (const float*)d_in[12];
    const float* b_ih_l1   = (const float*)d_in[13];
    const float* b_hh_l1   = (const float*)d_in[14];
    const float* w_ih_l1r  = (const float*)d_in[15];
    const float* w_hh_l1r  = (const float*)d_in[16];
    const float* b_ih_l1r  = (const float*)d_in[17];
    const float* b_hh_l1r  = (const float*)d_in[18];
    const float* linear_w  = (const float*)d_in[19];
    const float* linear_b  = (const float*)d_in[20];
    const float* start_tr  = (const float*)d_in[21];
    const float* end_tr    = (const float*)d_in[22];
    const float* trans     = (const float*)d_in[23];
    (void)in_sizes; (void)n_in;

    // ---- one merged fp16 conversion launch (embeds row-permuted to r-major)
    conv_all<<<(CONV_TOTAL4 + 255) / 256, 256>>>(embeds, w_ih_l0, w_ih_l0r,
                                                 w_ih_l1, w_ih_l1r);

    dim3 ggrid(8, 256);   // N/128 x M/128

    // layer 0
    gemm_tc<0><<<ggrid, 256>>>(768, b_ih_l0, b_hh_l0, b_ih_l0r, b_hh_l0r);
    lstm_kernel<<<128, 512>>>(w_hh_l0, w_hh_l0r, 0);

    // layer 1 (A = g_H0h)
    gemm_tc<1><<<ggrid, 256>>>(256, b_ih_l1, b_hh_l1, b_ih_l1r, b_hh_l1r);
    lstm_kernel<<<128, 512>>>(w_hh_l1, w_hh_l1r, 1);

    // fused emissions + CRF
    crf_kernel<<<64, 256>>>(tags, mask, start_tr, end_tr, trans, linear_w, linear_b);
    finish_kernel<<<1, 64>>>((float*)d_out, out_size);
}

// round 15
// speedup vs baseline: 1.2252x; 1.0217x over previous
#include <cuda_runtime.h>
#include <cuda_fp16.h>
#include <cuda_bf16.h>
#include <cstdint>

// Problem constants
#define BB 64
#define TT 512
#define EE 768
#define HH 128      // hidden per direction
#define KK 11

// ---------------------------------------------------------------------------
// Scratch (device globals; no dynamic allocation allowed)
// ---------------------------------------------------------------------------
__device__ __half g_XPh[(size_t)TT * BB * 1024];  // gate x-contributions (fp16)
__device__ __half g_Eh[(size_t)BB * TT * EE];     // embeds (fp16, r-major: r=t*64+b)
__device__ __half g_W0h[1024 * 768];              // [fwd;rev] w_ih layer0 (fp16)
__device__ __half g_W1h[1024 * 256];              // [fwd;rev] w_ih layer1 (fp16)
__device__ __half g_H0h[(size_t)TT * BB * 256];   // layer0 h (fp16, gemm1 A)
__device__ __half g_H1h[(size_t)TT * BB * 256];   // layer1 h (fp16, crf input)
__device__ float  g_ND[BB];                       // num - den per batch

__device__ __forceinline__ float tanha(float x) {
    float r; asm("tanh.approx.f32 %0, %1;" : "=f"(r) : "f"(x)); return r;
}
__device__ __forceinline__ float sigt(float x) {   // sigmoid via tanh
    return fmaf(0.5f, tanha(0.5f * x), 0.5f);
}
__device__ __forceinline__ __half2 u2h2(unsigned int u) {
    __half2 r; *reinterpret_cast<unsigned int*>(&r) = u; return r;
}
__device__ __forceinline__ unsigned h2u(__half2 h) {
    return *reinterpret_cast<unsigned*>(&h);
}
__device__ __forceinline__ void mma_f16(float* d, const unsigned* a, const unsigned* b) {
    asm volatile(
        "mma.sync.aligned.m16n8k16.row.col.f32.f16.f16.f32 "
        "{%0,%1,%2,%3},{%4,%5,%6,%7},{%8,%9},{%0,%1,%2,%3};"
        : "+f"(d[0]), "+f"(d[1]), "+f"(d[2]), "+f"(d[3])
        : "r"(a[0]), "r"(a[1]), "r"(a[2]), "r"(a[3]), "r"(b[0]), "r"(b[1]));
}
__device__ __forceinline__ unsigned smem_u32(const void* p) {
    unsigned a;
    asm("{ .reg .u64 t; cvta.to.shared.u64 t, %1; cvt.u32.u64 %0, t; }"
        : "=r"(a) : "l"(p));
    return a;
}
__device__ __forceinline__ void ldsm_x4(unsigned& r0, unsigned& r1,
                                        unsigned& r2, unsigned& r3, unsigned addr) {
    asm volatile("ldmatrix.sync.aligned.m8n8.x4.shared.b16 {%0,%1,%2,%3}, [%4];"
                 : "=r"(r0), "=r"(r1), "=r"(r2), "=r"(r3) : "r"(addr));
}
__device__ __forceinline__ void cp_async16(unsigned saddr, const void* gaddr) {
    asm volatile("cp.async.cg.shared.global [%0], [%1], 16;"
                 :: "r"(saddr), "l"(gaddr) : "memory");
}
__device__ __forceinline__ void cp_commit() {
    asm volatile("cp.async.commit_group;" ::: "memory");
}
__device__ __forceinline__ void cp_wait0() {
    asm volatile("cp.async.wait_group 0;" ::: "memory");
}

// ---------------------------------------------------------------------------
// Merged fp32 -> fp16 conversion (one launch).
// embeds row-permuted into r-major (r = t*64+b); both sides coalesced.
// ---------------------------------------------------------------------------
#define N_EMB (BB * TT * EE)     // 25165824
#define N_W0  (512 * 768)        // 393216
#define N_W1  (512 * 256)        // 131072
#define CONV_TOTAL4 ((N_EMB + 2 * N_W0 + 2 * N_W1) / 4)
#define E4 (EE / 4)              // 192 float4 per row

__global__ __launch_bounds__(256) void conv_all(
    const float* __restrict__ emb,
    const float* __restrict__ w0f, const float* __restrict__ w0r,
    const float* __restrict__ w1f, const float* __restrict__ w1r)
{
    long i4 = (long)blockIdx.x * 256 + threadIdx.x;
    if (i4 >= CONV_TOTAL4) return;
    long i = i4 * 4;

    const float* src;
    __half* dst;
    long soff, doff;
    if (i < N_EMB) {
        long r = i4 / E4;
        long e4 = i4 - r * E4;
        long b = r & 63, t = r >> 6;
        soff = (b * TT + t) * EE + e4 * 4;
        doff = i;
        src = emb; dst = g_Eh;
    } else if (i < N_EMB + N_W0)            { src = w0f; dst = g_W0h; soff = doff = i - N_EMB; }
    else if (i < N_EMB + 2 * N_W0)          { src = w0r; dst = g_W0h + N_W0; soff = doff = i - N_EMB - N_W0; }
    else if (i < N_EMB + 2 * N_W0 + N_W1)   { src = w1f; dst = g_W1h; soff = doff = i - N_EMB - 2 * N_W0; }
    else                                    { src = w1r; dst = g_W1h + N_W1; soff = doff = i - N_EMB - 2 * N_W0 - N_W1; }

    float4 f = *reinterpret_cast<const float4*>(src + soff);
    uint2 v;
    v.x = h2u(__floats2half2_rn(f.x, f.y));
    v.y = h2u(__floats2half2_rn(f.z, f.w));
    *reinterpret_cast<uint2*>(dst + doff) = v;
}

// ---------------------------------------------------------------------------
// fp16 tensor-core GEMM (fp32 accum), ldmatrix + cp.async double buffer, BK=32.
//   XPh[r][n] = A[r][:].W[n][:] + bias[n]
//   AMODE 0: A=g_Eh (r-major 768), W=g_W0h;  AMODE 1: A=g_H0h (256), W=g_W1h
// Tile BM=128, BN=128, BK=32 (two 16-k slabs); 8 warps (2m x 4n), warp 64x32.
// Slab SMEM: row-major [row][16 halves], chunk swizzle c^=((row>>2)&1).
// cp.async.cg bypasses L1 on the fill path (L1 is the measured bottleneck).
// ---------------------------------------------------------------------------
#define GBK 32
#define SLAB (128 * 16)              // halves per slab
#define SLABB (SLAB * 2)             // bytes per slab

template<int AMODE>
__global__ __launch_bounds__(256, 2) void gemm_tc(
    int Kdim,
    const float* __restrict__ biF, const float* __restrict__ bhF,
    const float* __restrict__ biR, const float* __restrict__ bhR)
{
    __shared__ __half As[2][2][SLAB];   // [buf][slab]
    __shared__ __half Bs[2][2][SLAB];
    __shared__ float bias[128];

    const int tid  = threadIdx.x;
    const int lane = tid & 31, wid = tid >> 5;
    const int wm = wid >> 2, wn = wid & 3;        // 2 x 4 warp grid
    const int g = lane >> 2, tig = lane & 3;
    const int row0 = blockIdx.y * 128;
    const int col0 = blockIdx.x * 128;

    if (tid < 128) {
        int n = col0 + tid;
        bias[tid] = (n < 512) ? (biF[n] + bhF[n]) : (biR[n - 512] + bhR[n - 512]);
    }

    // global load mapping: thread covers row r=(tid>>1), k-halves ak + {0,16}
    const int arow = tid >> 1;             // 0..127
    const int ak   = (tid & 1) * 8;        // 0 or 8 within each slab
    const size_t aoff = (size_t)(row0 + arow) * (size_t)Kdim;
    const __half* Ah = (AMODE == 0) ? g_Eh : g_H0h;
    const __half* Wb = (AMODE == 0) ? g_W0h : g_W1h;
    const __half* wrow = Wb + (size_t)(col0 + arow) * Kdim;

    // swizzled STS index (halves within slab) + cp.async dst addresses
    const int schunk = (ak >> 3) ^ ((arow >> 2) & 1);
    const int sIdx = arow * 16 + schunk * 8;
    unsigned dstA[2][2], dstB[2][2];
#pragma unroll
    for (int bu = 0; bu < 2; ++bu)
#pragma unroll
        for (int s = 0; s < 2; ++s) {
            dstA[bu][s] = smem_u32(&As[bu][s][sIdx]);
            dstB[bu][s] = smem_u32(&Bs[bu][s][sIdx]);
        }

    // ldmatrix per-thread byte offsets within a slab
    unsigned offA[4];
#pragma unroll
    for (int mt = 0; mt < 4; ++mt) {
        int row = wm * 64 + mt * 16 + (lane & 7) + ((lane >> 3) & 1) * 8;
        int ch  = ((lane >> 4) & 1) ^ ((row >> 2) & 1);
        offA[mt] = (unsigned)(row * 32 + ch * 16);
    }
    unsigned offB[2];
#pragma unroll
    for (int p = 0; p < 2; ++p) {
        int row = wn * 32 + p * 16 + ((lane >> 4) & 1) * 8 + (lane & 7);
        int ch  = ((lane >> 3) & 1) ^ ((row >> 2) & 1);
        offB[p] = (unsigned)(row * 32 + ch * 16);
    }
    const unsigned baseA[2] = { smem_u32(As[0][0]), smem_u32(As[1][0]) };
    const unsigned baseB[2] = { smem_u32(Bs[0][0]), smem_u32(Bs[1][0]) };

    float c[4][4][4];
#pragma unroll
    for (int i = 0; i < 4; i++)
#pragma unroll
        for (int j = 0; j < 4; j++)
#pragma unroll
            for (int q = 0; q < 4; q++) c[i][j][q] = 0.f;

    const int niter = Kdim / GBK;

    // prologue: chunk 0 -> buf 0 via cp.async
    cp_async16(dstA[0][0], Ah + aoff + ak);
    cp_async16(dstA[0][1], Ah + aoff + 16 + ak);
    cp_async16(dstB[0][0], wrow + ak);
    cp_async16(dstB[0][1], wrow + 16 + ak);
    cp_commit();
    cp_wait0();
    __syncthreads();

#pragma unroll 1
    for (int i = 0; i < niter; ++i) {
        const int pb = i & 1;
        if (i + 1 < niter) {
            const int k0 = (i + 1) * GBK;
            const int nb = pb ^ 1;
            cp_async16(dstA[nb][0], Ah + aoff + k0 + ak);
            cp_async16(dstA[nb][1], Ah + aoff + k0 + 16 + ak);
            cp_async16(dstB[nb][0], wrow + k0 + ak);
            cp_async16(dstB[nb][1], wrow + k0 + 16 + ak);
            cp_commit();
        }

        // two 16-k slabs from buf pb
#pragma unroll
        for (int s = 0; s < 2; ++s) {
            const unsigned bA = baseA[pb] + s * SLABB;
            const unsigned bB = baseB[pb] + s * SLABB;
            unsigned af[4][4], bf[4][2];
#pragma unroll
            for (int mt = 0; mt < 4; ++mt)
                ldsm_x4(af[mt][0], af[mt][1], af[mt][2], af[mt][3], bA + offA[mt]);
#pragma unroll
            for (int p = 0; p < 2; ++p)
                ldsm_x4(bf[2 * p][0], bf[2 * p][1], bf[2 * p + 1][0], bf[2 * p + 1][1],
                        bB + offB[p]);
#pragma unroll
            for (int mt = 0; mt < 4; ++mt)
#pragma unroll
                for (int nt = 0; nt < 4; ++nt)
                    mma_f16(c[mt][nt], af[mt], bf[nt]);
        }

        if (i + 1 < niter) cp_wait0();
        __syncthreads();
    }

    // epilogue: XPh(row,col) = c + bias, packed half2
#pragma unroll
    for (int mt = 0; mt < 4; ++mt) {
#pragma unroll
        for (int nt = 0; nt < 4; ++nt) {
            int r  = row0 + wm * 64 + mt * 16 + g;
            int cb = wn * 32 + nt * 8 + 2 * tig;
            int col = col0 + cb;
            unsigned p0 = h2u(__floats2half2_rn(c[mt][nt][0] + bias[cb],
                                                c[mt][nt][1] + bias[cb + 1]));
            unsigned p1 = h2u(__floats2half2_rn(c[mt][nt][2] + bias[cb],
                                                c[mt][nt][3] + bias[cb + 1]));
            *reinterpret_cast<unsigned*>(&g_XPh[(size_t)r * 1024 + col]) = p0;
            *reinterpret_cast<unsigned*>(&g_XPh[(size_t)(r + 8) * 1024 + col]) = p1;
        }
    }
}

// ---------------------------------------------------------------------------
// LSTM recurrence: one block per (batch, dir). 512 threads = 16 warps.
// (unchanged — measured best)
// ---------------------------------------------------------------------------
__global__ __launch_bounds__(512) void lstm_kernel(
    const float* __restrict__ whh_fwd, const float* __restrict__ whh_rev, int layer)
{
    __shared__ uint4 hbuf4[2][16];   // 2 x 128 halves

    const int b   = blockIdx.x >> 1;
    const int dir = blockIdx.x & 1;
    const float* whh = dir ? whh_rev : whh_fwd;

    const int lane = threadIdx.x & 31;
    const int wid  = threadIdx.x >> 5;
    const int u    = wid * 8 + (lane & 7);
    const int gate = lane >> 3;
    const int wrow_idx = gate * 128 + u;

    // weights -> registers (fp16)
    __half2 W[64];
    {
        const float4* wr4 = reinterpret_cast<const float4*>(whh + (size_t)wrow_idx * 128);
#pragma unroll
        for (int i = 0; i < 32; ++i) {
            float4 f = wr4[i];
            W[2 * i]     = __floats2half2_rn(f.x, f.y);
            W[2 * i + 1] = __floats2half2_rn(f.z, f.w);
        }
    }
    if (threadIdx.x < 16) hbuf4[0][threadIdx.x] = make_uint4(0u, 0u, 0u, 0u);
    float cst = 0.f;
    __syncthreads();

    const long xstride = dir ? -(long)(BB * 1024) : (long)(BB * 1024);
    const long hstride = dir ? -(long)(BB * 256)  : (long)(BB * 256);
    const size_t hbase = (size_t)(dir ? (TT - 1) : 0) * (BB * 256)
                       + (size_t)b * 256 + dir * 128 + u;
    const __half* xp_p = g_XPh + (size_t)(dir ? (TT - 1) : 0) * (BB * 1024)
                               + (size_t)b * 1024 + dir * 512 + wrow_idx;
    __half* hout_p = (layer ? g_H1h : g_H0h) + hbase;

    __half xp = *xp_p;

#pragma unroll 2
    for (int t = 0; t < TT; ++t) {
        const __half* pf = xp_p + ((t < TT - 1) ? xstride : 0);
        __half xpn = *pf;

        const uint4* hb = hbuf4[t & 1];
        __half2 s0 = __floats2half2_rn(0.f, 0.f);
        __half2 s1 = s0, s2 = s0, s3 = s0;
#pragma unroll
        for (int k = 0; k < 4; ++k) {
            uint4 ha = hb[4 * k];
            uint4 hc = hb[4 * k + 1];
            uint4 hd = hb[4 * k + 2];
            uint4 he = hb[4 * k + 3];
            s0 = __hfma2(W[16 * k + 0],  u2h2(ha.x), s0);
            s1 = __hfma2(W[16 * k + 1],  u2h2(ha.y), s1);
            s2 = __hfma2(W[16 * k + 2],  u2h2(ha.z), s2);
            s3 = __hfma2(W[16 * k + 3],  u2h2(ha.w), s3);
            s0 = __hfma2(W[16 * k + 4],  u2h2(hc.x), s0);
            s1 = __hfma2(W[16 * k + 5],  u2h2(hc.y), s1);
            s2 = __hfma2(W[16 * k + 6],  u2h2(hc.z), s2);
            s3 = __hfma2(W[16 * k + 7],  u2h2(hc.w), s3);
            s0 = __hfma2(W[16 * k + 8],  u2h2(hd.x), s0);
            s1 = __hfma2(W[16 * k + 9],  u2h2(hd.y), s1);
            s2 = __hfma2(W[16 * k + 10], u2h2(hd.z), s2);
            s3 = __hfma2(W[16 * k + 11], u2h2(hd.w), s3);
            s0 = __hfma2(W[16 * k + 12], u2h2(he.x), s0);
            s1 = __hfma2(W[16 * k + 13], u2h2(he.y), s1);
            s2 = __hfma2(W[16 * k + 14], u2h2(he.z), s2);
            s3 = __hfma2(W[16 * k + 15], u2h2(he.w), s3);
        }
        __half2 sh = __hadd2(__hadd2(s0, s1), __hadd2(s2, s3));
        __half  gh = __hadd(__hadd(__low2half(sh), __high2half(sh)), xp);
        const float gval = __half2float(gh);

        const float act = (gate == 2) ? tanha(gval) : sigt(gval);

        const int src = lane & 7;
        float iv = __shfl_sync(0xffffffffu, act, src);
        float fv = __shfl_sync(0xffffffffu, act, src + 8);
        float gv = __shfl_sync(0xffffffffu, act, src + 16);
        float ov = __shfl_sync(0xffffffffu, act, src + 24);

        if (lane < 8) {
            float cn = fv * cst + iv * gv;
            cst = cn;
            float hn = ov * tanha(cn);
            __half hcvt = __float2half_rn(hn);
            reinterpret_cast<__half*>(&hbuf4[(t & 1) ^ 1][0])[u] = hcvt;
            *hout_p = hcvt;
        }
        xp = xpn;
        xp_p += xstride;
        hout_p += hstride;
        __syncthreads();
    }
}

// ---------------------------------------------------------------------------
// CRF (fused emissions): one block per batch.  (unchanged)
// ---------------------------------------------------------------------------
__global__ __launch_bounds__(256) void crf_kernel(
    const int* __restrict__ tags, const void* __restrict__ maskraw,
    const float* __restrict__ start_t, const float* __restrict__ end_t,
    const float* __restrict__ trans,
    const float* __restrict__ lw, const float* __restrict__ lb)
{
    __shared__ float ems[TT * 12];
    __shared__ float redf[256];
    __shared__ int   redi[256];
    __shared__ unsigned char maskb[TT];
    __shared__ float s_num;

    const int b = blockIdx.x;
    const int tid = threadIdx.x;

    {
        const unsigned char* mc = reinterpret_cast<const unsigned char*>(maskraw);
        const bool bytewise = (mc[1] != 0);
        const int* mi = reinterpret_cast<const int*>(maskraw);
        for (int t = tid; t < TT; t += 256) {
            maskb[t] = bytewise ? (mc[(size_t)b * TT + t] != 0)
                                : (mi[(size_t)b * TT + t] != 0);
        }
    }

    // ---- fused emissions
    for (int base = tid; base < TT * 16; base += 256) {
        int t = base >> 4, n = base & 15;
        if (n < KK) {
            const uint4*  h4 = reinterpret_cast<const uint4*>(
                &g_H1h[((size_t)t * BB + b) * 256]);
            const float4* w4 = reinterpret_cast<const float4*>(lw + (size_t)n * 256);
            float acc = 0.f;
#pragma unroll 8
            for (int k = 0; k < 32; ++k) {
                uint4 hv = h4[k];
                float4 w0 = w4[2 * k], w1 = w4[2 * k + 1];
                float2 a0 = __half22float2(u2h2(hv.x));
                float2 a1 = __half22float2(u2h2(hv.y));
                float2 a2 = __half22float2(u2h2(hv.z));
                float2 a3 = __half22float2(u2h2(hv.w));
                acc += a0.x * w0.x + a0.y * w0.y + a1.x * w0.z + a1.y * w0.w;
                acc += a2.x * w1.x + a2.y * w1.y + a3.x * w1.z + a3.y * w1.w;
            }
            ems[t * 12 + n] = acc + lb[n];
        }
    }
    __syncthreads();

    // ---- numerator (parallel over t)
    float part = 0.f;
    int   cnt  = 0;
    for (int t = tid; t < TT; t += 256) cnt += maskb[t] ? 1 : 0;
    for (int t = 1 + tid; t < TT; t += 256) {
        if (maskb[t]) {
            int tp = tags[(size_t)b * TT + t - 1];
            int tc = tags[(size_t)b * TT + t];
            part += trans[tp * KK + tc] + ems[t * 12 + tc];
        }
    }
    redf[tid] = part; redi[tid] = cnt;
    __syncthreads();
    for (int s = 128; s > 0; s >>= 1) {
        if (tid < s) { redf[tid] += redf[tid + s]; redi[tid] += redi[tid + s]; }
        __syncthreads();
    }
    if (tid == 0) {
        int t0 = tags[(size_t)b * TT];
        int seqEnd = redi[0] - 1;
        s_num = start_t[t0] + ems[t0] + redf[0]
              + end_t[tags[(size_t)b * TT + seqEnd]];
    }
    __syncthreads();

    // ---- denominator (warp 0, baseline-rescaled forward algorithm)
    if (tid < 32) {
        const int lane = tid;
        float etcol[KK];
        if (lane < KK) {
#pragma unroll
            for (int i = 0; i < KK; i++) etcol[i] = __expf(trans[i * KK + lane]);
        } else {
#pragma unroll
            for (int i = 0; i < KK; i++) etcol[i] = 0.f;
        }
        float score = (lane < KK) ? (start_t[lane] + ems[lane]) : -1e30f;

        for (int t = 1; t < TT; ++t) {
            if (maskb[t]) {
                float m = __shfl_sync(0xffffffffu, score, 0);
                float e = __expf(score - m);
                float dot = 0.f;
#pragma unroll
                for (int i = 0; i < KK; i++)
                    dot = fmaf(__shfl_sync(0xffffffffu, e, i), etcol[i], dot);
                float nxt = m + __logf(dot) + ems[t * 12 + lane];
                if (lane < KK) score = nxt;
            }
        }
        float v = (lane < KK) ? (score + end_t[lane]) : -1e30f;
        float m = v;
#pragma unroll
        for (int off = 16; off > 0; off >>= 1)
            m = fmaxf(m, __shfl_xor_sync(0xffffffffu, m, off));
        float e = __expf(v - m);
#pragma unroll
        for (int off = 16; off > 0; off >>= 1)
            e += __shfl_xor_sync(0xffffffffu, e, off);
        float den = m + __logf(e);
        if (lane == 0) g_ND[b] = s_num - den;
    }
}

__global__ void finish_kernel(float* __restrict__ out, int out_n)
{
    __shared__ float s[64];
    int tid = threadIdx.x;
    s[tid] = g_ND[tid];
    __syncthreads();
    for (int st = 32; st > 0; st >>= 1) {
        if (tid < st) s[tid] += s[tid + st];
        __syncthreads();
    }
    if (tid == 0) out[0] = -s[0] / 64.f;
    if (tid > 0 && tid < out_n) out[tid] = 0.f;
}

// ---------------------------------------------------------------------------
extern "C" void kernel_launch(void* const* d_in, const int* in_sizes, int n_in,
                              void* d_out, int out_size)
{
    const float* embeds    = (const float*)d_in[0];
    const int*   tags      = (const int*)d_in[1];
    const void*  mask      = d_in[2];
    const float* w_ih_l0   = (const float*)d_in[3];
    const float* w_hh_l0   = (const float*)d_in[4];
    const float* b_ih_l0   = (const float*)d_in[5];
    const float* b_hh_l0   = (const float*)d_in[6];
    const float* w_ih_l0r  = (const float*)d_in[7];
    const float* w_hh_l0r  = (const float*)d_in[8];
    const float* b_ih_l0r  = (const float*)d_in[9];
    const float* b_hh_l0r  = (const float*)d_in[10];
    const float* w_ih_l1   = (const float*)d_in[11];
    const float* w_hh_l1   = (const float*)d_in[12];
    const float* b_ih_l1   = (const float*)d_in[13];
    const float* b_hh_l1   = (const float*)d_in[14];
    const float* w_ih_l1r  = (const float*)d_in[15];
    const float* w_hh_l1r  = (const float*)d_in[16];
    const float* b_ih_l1r  = (const float*)d_in[17];
    const float* b_hh_l1r  = (const float*)d_in[18];
    const float* linear_w  = (const float*)d_in[19];
    const float* linear_b  = (const float*)d_in[20];
    const float* start_tr  = (const float*)d_in[21];
    const float* end_tr    = (const float*)d_in[22];
    const float* trans     = (const float*)d_in[23];
    (void)in_sizes; (void)n_in;

    // Maximize smem carveout so 2 gemm CTAs fit per SM
    cudaFuncSetAttribute(gemm_tc<0>,
        cudaFuncAttributePreferredSharedMemoryCarveout, 100);
    cudaFuncSetAttribute(gemm_tc<1>,
        cudaFuncAttributePreferredSharedMemoryCarveout, 100);

    // ---- one merged fp16 conversion launch (embeds row-permuted to r-major)
    conv_all<<<(CONV_TOTAL4 + 255) / 256, 256>>>(embeds, w_ih_l0, w_ih_l0r,
                                                 w_ih_l1, w_ih_l1r);

    dim3 ggrid(8, 256);   // N/128 x M/128

    // layer 0
    gemm_tc<0><<<ggrid, 256>>>(768, b_ih_l0, b_hh_l0, b_ih_l0r, b_hh_l0r);
    lstm_kernel<<<128, 512>>>(w_hh_l0, w_hh_l0r, 0);

    // layer 1 (A = g_H0h)
    gemm_tc<1><<<ggrid, 256>>>(256, b_ih_l1, b_hh_l1, b_ih_l1r, b_hh_l1r);
    lstm_kernel<<<128, 512>>>(w_hh_l1, w_hh_l1r, 1);

    // fused emissions + CRF
    crf_kernel<<<64, 256>>>(tags, mask, start_tr, end_tr, trans, linear_w, linear_b);
    finish_kernel<<<1, 64>>>((float*)d_out, out_size);
}